// round 6
// baseline (speedup 1.0000x reference)
#include <cuda_runtime.h>
#include <mma.h>
#include <math.h>
#include <cstdint>

using namespace nvcuda;

#define B_   2
#define LQ_  1024
#define LK_  1024
#define D_   1024
#define H_   16
#define DH_  64
#define BH_  (B_ * H_)
#define NEG_BIG (-3.402823466e38f)

#define TF32(x) wmma::__float_to_tf32(x)

// ---------------- scratch ----------------------------------------------------
__device__ float g_q[B_ * LQ_ * D_];
__device__ float g_k[B_ * LK_ * D_];
__device__ float g_v[B_ * LK_ * D_];
__device__ float g_s[(size_t)BH_ * LQ_ * LK_];   // 134 MB scores/probs
__device__ float g_att[B_ * LQ_ * D_];
__device__ int   g_mask_kind;

// ---------------- cp.async helpers ------------------------------------------
__device__ __forceinline__ void cp16(unsigned int dst, const void* src) {
    asm volatile("cp.async.cg.shared.global [%0], [%1], 16;\n" :: "r"(dst), "l"(src));
}
__device__ __forceinline__ void cp_commit() {
    asm volatile("cp.async.commit_group;\n" ::: "memory");
}
__device__ __forceinline__ void cp_wait_all() {
    asm volatile("cp.async.wait_group 0;\n" ::: "memory");
}

// ---------------- mask dtype detection --------------------------------------
__global__ void detect_mask_kernel(const unsigned int* m) {
    if (threadIdx.x == 0 && blockIdx.x == 0) {
        int all01 = 1, allf = 1;
        for (int i = 0; i < 512; i++) {
            unsigned v = m[i];
            if (v > 1u) all01 = 0;
            if (v != 0u && v != 0x3F800000u) allf = 0;
        }
        g_mask_kind = all01 ? 0 : (allf ? 1 : 2);
    }
}

__device__ __forceinline__ bool mask_true(const void* m, int kind, int idx) {
    if (kind == 0) return ((const int*)m)[idx] != 0;
    if (kind == 1) return ((const float*)m)[idx] != 0.0f;
    return ((const unsigned char*)m)[idx] != 0;
}

// ---------------- tf32 GEMM: C[2048,1024] = A @ W^T + bias ------------------
// BM=128 BN=128 BK=32, 256 thr, 8 warps (2M x 4N), warp tile 64x32 = 4x2 frags.
// cp.async double-buffered smem; tf32 RN conversion applied in fragments.
__global__ __launch_bounds__(256) void gemm_tf32(
    const float* __restrict__ A, const float* __restrict__ W,
    const float* __restrict__ bias, float* __restrict__ C)
{
    extern __shared__ float dsm[];
    // As[2][128][36], Ws[2][128][36], Bs[16][132]
    float* As = dsm;
    float* Ws = dsm + 2 * 128 * 36;
    float* Bs = dsm + 4 * 128 * 36;

    const int tid = threadIdx.x;
    const int w = tid >> 5;
    const int m0 = blockIdx.y * 128, n0 = blockIdx.x * 128;
    const int wm = w >> 2;   // 0..1 -> 64-row half
    const int wn = w & 3;    // 0..3 -> 32-col quarter

    // bias tile (16 identical rows)
    for (int i = tid; i < 16 * 128; i += 256)
        Bs[(i >> 7) * 132 + (i & 127)] = bias[n0 + (i & 127)];

    const unsigned int sA = (unsigned int)__cvta_generic_to_shared(As);
    const unsigned int sW = (unsigned int)__cvta_generic_to_shared(Ws);

    // per-thread copy map: 4 float4 per matrix per tile
    // f = tid + u*256 ; row = f>>3 (0..127) ; col = (f&7)*4
    int crow[4], ccol[4];
    #pragma unroll
    for (int u = 0; u < 4; u++) { int f = tid + u * 256; crow[u] = f >> 3; ccol[u] = (f & 7) * 4; }

    // prologue: tile 0 into buffer 0
    #pragma unroll
    for (int u = 0; u < 4; u++) {
        cp16(sA + (crow[u] * 36 + ccol[u]) * 4, &A[(size_t)(m0 + crow[u]) * 1024 + ccol[u]]);
        cp16(sW + (crow[u] * 36 + ccol[u]) * 4, &W[(size_t)(n0 + crow[u]) * 1024 + ccol[u]]);
    }
    cp_commit();

    wmma::fragment<wmma::accumulator, 16, 16, 8, float> c[4][2];
    __syncthreads();   // Bs ready
    #pragma unroll
    for (int i = 0; i < 4; i++)
        #pragma unroll
        for (int j = 0; j < 2; j++)
            wmma::load_matrix_sync(c[i][j], &Bs[wn * 32 + j * 16], 132, wmma::mem_row_major);

    int buf = 0;
    for (int kt = 0; kt < 1024; kt += 32, buf ^= 1) {
        cp_wait_all();
        __syncthreads();

        if (kt + 32 < 1024) {
            const int nb = buf ^ 1;
            #pragma unroll
            for (int u = 0; u < 4; u++) {
                cp16(sA + (nb * 128 * 36 + crow[u] * 36 + ccol[u]) * 4,
                     &A[(size_t)(m0 + crow[u]) * 1024 + kt + 32 + ccol[u]]);
                cp16(sW + (nb * 128 * 36 + crow[u] * 36 + ccol[u]) * 4,
                     &W[(size_t)(n0 + crow[u]) * 1024 + kt + 32 + ccol[u]]);
            }
            cp_commit();
        }

        const float* Ab = As + buf * 128 * 36;
        const float* Wb = Ws + buf * 128 * 36;

        #pragma unroll
        for (int kk = 0; kk < 32; kk += 8) {
            wmma::fragment<wmma::matrix_a, 16, 16, 8, wmma::precision::tf32, wmma::row_major> a[4];
            wmma::fragment<wmma::matrix_b, 16, 16, 8, wmma::precision::tf32, wmma::col_major> bf[2];
            #pragma unroll
            for (int i = 0; i < 4; i++) {
                wmma::load_matrix_sync(a[i], &Ab[(wm * 64 + i * 16) * 36 + kk], 36);
                #pragma unroll
                for (int t = 0; t < a[i].num_elements; t++) a[i].x[t] = TF32(a[i].x[t]);
            }
            #pragma unroll
            for (int j = 0; j < 2; j++) {
                wmma::load_matrix_sync(bf[j], &Wb[(wn * 32 + j * 16) * 36 + kk], 36);
                #pragma unroll
                for (int t = 0; t < bf[j].num_elements; t++) bf[j].x[t] = TF32(bf[j].x[t]);
            }
            #pragma unroll
            for (int i = 0; i < 4; i++)
                #pragma unroll
                for (int j = 0; j < 2; j++)
                    wmma::mma_sync(c[i][j], a[i], bf[j], c[i][j]);
        }
    }

    #pragma unroll
    for (int i = 0; i < 4; i++)
        #pragma unroll
        for (int j = 0; j < 2; j++)
            wmma::store_matrix_sync(
                &C[(size_t)(m0 + wm * 64 + i * 16) * 1024 + n0 + wn * 32 + j * 16],
                c[i][j], 1024, wmma::mem_row_major);
}

static const int GEMM_SMEM = (4 * 128 * 36 + 16 * 132) * 4;   // 82176 B

// ---------------- scores: S = (Q*scale) Kh^T + bias/mask --------------------
__global__ __launch_bounds__(256) void scores_wmma(
    const void* __restrict__ mask, const float* __restrict__ lb)
{
    extern __shared__ float buf[];
    float* Qs = buf;                 // 128 x 72
    float* Ks = buf + 128 * 72;      // 128 x 72
    float* Ss = buf;                 // reused: 128 x 132

    const int tid = threadIdx.x;
    const int w = tid >> 5;
    const int k0 = blockIdx.x * 128, q0 = blockIdx.y * 128;
    const int bh = blockIdx.z;
    const int b = bh >> 4, h = bh & 15;
    const int hc = h * DH_;
    const int wm = w >> 2, wn = w & 3;

    for (int i = tid * 4; i < 128 * 64; i += 1024) {
        int r = i >> 6, cc = i & 63;
        float4 qv = *(const float4*)&g_q[(size_t)(b * LQ_ + q0 + r) * D_ + hc + cc];
        *(float4*)&Qs[r * 72 + cc] = make_float4(
            TF32(qv.x * 0.125f), TF32(qv.y * 0.125f), TF32(qv.z * 0.125f), TF32(qv.w * 0.125f));
        float4 kv = *(const float4*)&g_k[(size_t)(b * LK_ + k0 + r) * D_ + hc + cc];
        *(float4*)&Ks[r * 72 + cc] = make_float4(TF32(kv.x), TF32(kv.y), TF32(kv.z), TF32(kv.w));
    }
    __syncthreads();

    wmma::fragment<wmma::accumulator, 16, 16, 8, float> s[4][2];
    #pragma unroll
    for (int i = 0; i < 4; i++)
        #pragma unroll
        for (int j = 0; j < 2; j++)
            wmma::fill_fragment(s[i][j], 0.0f);

    #pragma unroll
    for (int kk = 0; kk < 64; kk += 8) {
        wmma::fragment<wmma::matrix_a, 16, 16, 8, wmma::precision::tf32, wmma::row_major> a[4];
        wmma::fragment<wmma::matrix_b, 16, 16, 8, wmma::precision::tf32, wmma::col_major> bf[2];
        #pragma unroll
        for (int i = 0; i < 4; i++)
            wmma::load_matrix_sync(a[i], &Qs[(wm * 64 + i * 16) * 72 + kk], 72);
        #pragma unroll
        for (int j = 0; j < 2; j++)
            wmma::load_matrix_sync(bf[j], &Ks[(wn * 32 + j * 16) * 72 + kk], 72);
        #pragma unroll
        for (int i = 0; i < 4; i++)
            #pragma unroll
            for (int j = 0; j < 2; j++)
                wmma::mma_sync(s[i][j], a[i], bf[j], s[i][j]);
    }
    __syncthreads();

    #pragma unroll
    for (int i = 0; i < 4; i++)
        #pragma unroll
        for (int j = 0; j < 2; j++)
            wmma::store_matrix_sync(&Ss[(wm * 64 + i * 16) * 132 + wn * 32 + j * 16],
                                    s[i][j], 132, wmma::mem_row_major);
    __syncthreads();

    const int kind = g_mask_kind;
    for (int i = tid * 4; i < 128 * 128; i += 1024) {
        int r = i >> 7, cc = i & 127;
        int q = q0 + r;
        float4 v = *(float4*)&Ss[r * 132 + cc];
        const float* lbrow = lb + (size_t)(b * LQ_ + q) * LK_ + k0 + cc;
        float o[4] = {v.x, v.y, v.z, v.w};
        #pragma unroll
        for (int e = 0; e < 4; e++) {
            bool mk = mask_true(mask, kind, b * LK_ + k0 + cc + e);
            o[e] += mk ? NEG_BIG : lbrow[e];
        }
        *(float4*)&g_s[((size_t)bh * LQ_ + q) * LK_ + k0 + cc] =
            make_float4(o[0], o[1], o[2], o[3]);
    }
}

// ---------------- row softmax over LK=1024 ----------------------------------
__global__ __launch_bounds__(256) void softmax_kernel() {
    const size_t row = blockIdx.x;
    float* s = &g_s[row * LK_];
    const int tid = threadIdx.x;
    const int lane = tid & 31, wid = tid >> 5;

    float4 v = *(float4*)&s[tid * 4];
    float m = fmaxf(fmaxf(v.x, v.y), fmaxf(v.z, v.w));
    #pragma unroll
    for (int o = 16; o > 0; o >>= 1) m = fmaxf(m, __shfl_xor_sync(0xffffffffu, m, o));

    __shared__ float red[8], red2[8];
    if (lane == 0) red[wid] = m;
    __syncthreads();
    float bm = red[0];
    #pragma unroll
    for (int i = 1; i < 8; i++) bm = fmaxf(bm, red[i]);

    float e0 = __expf(v.x - bm), e1 = __expf(v.y - bm);
    float e2 = __expf(v.z - bm), e3 = __expf(v.w - bm);
    float sum = e0 + e1 + e2 + e3;
    #pragma unroll
    for (int o = 16; o > 0; o >>= 1) sum += __shfl_xor_sync(0xffffffffu, sum, o);
    if (lane == 0) red2[wid] = sum;
    __syncthreads();
    float tot = 0.0f;
    #pragma unroll
    for (int i = 0; i < 8; i++) tot += red2[i];

    float inv = 1.0f / tot;
    *(float4*)&s[tid * 4] = make_float4(e0 * inv, e1 * inv, e2 * inv, e3 * inv);
}

// ---------------- PV: att = P @ Vh ------------------------------------------
__global__ __launch_bounds__(256, 2) void pv_wmma() {
    __shared__ float Ps[128][36];
    __shared__ float Vs[32][72];

    const int tid = threadIdx.x;
    const int w = tid >> 5;
    const int m0 = blockIdx.x * 128;
    const int bh = blockIdx.y;
    const int b = bh >> 4, h = bh & 15;
    const int hc = h * DH_;
    const int wm = w >> 1, wn = w & 1;

    const int pr = tid >> 3, pc = (tid & 7) * 4;

    wmma::fragment<wmma::accumulator, 16, 16, 8, float> c[2][2];
    #pragma unroll
    for (int i = 0; i < 2; i++)
        #pragma unroll
        for (int j = 0; j < 2; j++)
            wmma::fill_fragment(c[i][j], 0.0f);

    float4 rp[4], rv[2];
    #pragma unroll
    for (int u = 0; u < 4; u++)
        rp[u] = *(const float4*)&g_s[((size_t)bh * LQ_ + m0 + pr + u * 32) * LK_ + pc];
    #pragma unroll
    for (int u = 0; u < 2; u++) {
        int idx = tid + u * 256;
        rv[u] = *(const float4*)&g_v[(size_t)(b * LK_ + (idx >> 4)) * D_ + hc + (idx & 15) * 4];
    }

    for (int kt = 0; kt < 1024; kt += 32) {
        #pragma unroll
        for (int u = 0; u < 4; u++)
            *(float4*)&Ps[pr + u * 32][pc] =
                make_float4(TF32(rp[u].x), TF32(rp[u].y), TF32(rp[u].z), TF32(rp[u].w));
        #pragma unroll
        for (int u = 0; u < 2; u++) {
            int idx = tid + u * 256;
            *(float4*)&Vs[idx >> 4][(idx & 15) * 4] =
                make_float4(TF32(rv[u].x), TF32(rv[u].y), TF32(rv[u].z), TF32(rv[u].w));
        }
        __syncthreads();

        if (kt + 32 < 1024) {
            #pragma unroll
            for (int u = 0; u < 4; u++)
                rp[u] = *(const float4*)&g_s[((size_t)bh * LQ_ + m0 + pr + u * 32) * LK_ + kt + 32 + pc];
            #pragma unroll
            for (int u = 0; u < 2; u++) {
                int idx = tid + u * 256;
                rv[u] = *(const float4*)&g_v[(size_t)(b * LK_ + kt + 32 + (idx >> 4)) * D_ + hc + (idx & 15) * 4];
            }
        }

        #pragma unroll
        for (int kk = 0; kk < 32; kk += 8) {
            wmma::fragment<wmma::matrix_a, 16, 16, 8, wmma::precision::tf32, wmma::row_major> a[2];
            wmma::fragment<wmma::matrix_b, 16, 16, 8, wmma::precision::tf32, wmma::row_major> bf[2];
            #pragma unroll
            for (int i = 0; i < 2; i++)
                wmma::load_matrix_sync(a[i], &Ps[wm * 32 + i * 16][kk], 36);
            #pragma unroll
            for (int j = 0; j < 2; j++)
                wmma::load_matrix_sync(bf[j], &Vs[kk][wn * 32 + j * 16], 72);
            #pragma unroll
            for (int i = 0; i < 2; i++)
                #pragma unroll
                for (int j = 0; j < 2; j++)
                    wmma::mma_sync(c[i][j], a[i], bf[j], c[i][j]);
        }
        __syncthreads();
    }

    #pragma unroll
    for (int i = 0; i < 2; i++)
        #pragma unroll
        for (int j = 0; j < 2; j++)
            wmma::store_matrix_sync(
                &g_att[(size_t)(b * LQ_ + m0 + wm * 32 + i * 16) * D_ + hc + wn * 32 + j * 16],
                c[i][j], 1024, wmma::mem_row_major);
}

// ---------------- launch ----------------------------------------------------
static const int SCORES_SMEM = 2 * 128 * 72 * 4;   // 73728 B

extern "C" void kernel_launch(void* const* d_in, const int* in_sizes, int n_in,
                              void* d_out, int out_size)
{
    const float* q    = (const float*)d_in[0];
    const float* k    = (const float*)d_in[1];
    const float* v    = (const float*)d_in[2];
    const float* Wq   = (const float*)d_in[3];
    const float* bq   = (const float*)d_in[4];
    const float* Wk   = (const float*)d_in[5];
    const float* bk   = (const float*)d_in[6];
    const float* Wv   = (const float*)d_in[7];
    const float* bv   = (const float*)d_in[8];
    const float* Wo   = (const float*)d_in[9];
    const float* bo   = (const float*)d_in[10];
    const float* lb   = (const float*)d_in[11];
    const void*  mask = (const void*)d_in[12];
    float* out = (float*)d_out;

    float *pq, *pk, *pv, *patt;
    cudaGetSymbolAddress((void**)&pq,   g_q);
    cudaGetSymbolAddress((void**)&pk,   g_k);
    cudaGetSymbolAddress((void**)&pv,   g_v);
    cudaGetSymbolAddress((void**)&patt, g_att);

    cudaFuncSetAttribute(gemm_tf32, cudaFuncAttributeMaxDynamicSharedMemorySize, GEMM_SMEM);
    cudaFuncSetAttribute(scores_wmma, cudaFuncAttributeMaxDynamicSharedMemorySize, SCORES_SMEM);

    detect_mask_kernel<<<1, 32>>>((const unsigned int*)mask);

    dim3 gproj(8, 16);   // N/128 x M/128
    gemm_tf32<<<gproj, 256, GEMM_SMEM>>>(q, Wq, bq, pq);
    gemm_tf32<<<gproj, 256, GEMM_SMEM>>>(k, Wk, bk, pk);
    gemm_tf32<<<gproj, 256, GEMM_SMEM>>>(v, Wv, bv, pv);

    scores_wmma<<<dim3(8, 8, BH_), 256, SCORES_SMEM>>>(mask, lb);

    softmax_kernel<<<BH_ * LQ_, 256>>>();

    pv_wmma<<<dim3(8, BH_), 256>>>();

    gemm_tf32<<<gproj, 256, GEMM_SMEM>>>(patt, Wo, bo, out);
}

// round 8
// speedup vs baseline: 2.2918x; 2.2918x over previous
#include <cuda_runtime.h>
#include <cuda_fp16.h>
#include <mma.h>
#include <math.h>
#include <cstdint>

using namespace nvcuda;

#define B_   2
#define LQ_  1024
#define LK_  1024
#define D_   1024
#define H_   16
#define DH_  64
#define BH_  (B_ * H_)
#define NEG_BIG (-3.402823466e38f)

// ---------------- scratch ----------------------------------------------------
__device__ __half g_xh[2048 * 1024];              // GEMM A staging (half)
__device__ __half g_wh[1024 * 1024];              // weight staging (half)
__device__ __half g_qh[2048 * 1024];              // projected Q (half)
__device__ __half g_kh[2048 * 1024];              // projected K (half)
__device__ __half g_vh[2048 * 1024];              // projected V (half)
__device__ float  g_s[(size_t)BH_ * LQ_ * LK_];   // scores fp32 (134 MB)
__device__ __half g_ph[(size_t)BH_ * LQ_ * LK_];  // probs half (67 MB)
__device__ float  g_att[2048 * 1024];             // attention out fp32
__device__ int    g_mask_kind;

// ---------------- helpers -----------------------------------------------------
__device__ __forceinline__ void cp16(unsigned int dst, const void* src) {
    asm volatile("cp.async.cg.shared.global [%0], [%1], 16;\n" :: "r"(dst), "l"(src));
}
__device__ __forceinline__ void cp_commit() {
    asm volatile("cp.async.commit_group;\n" ::: "memory");
}
__device__ __forceinline__ unsigned int smem_u32(const void* ptr) {
    unsigned int a;
    asm("{ .reg .u64 t; cvta.to.shared.u64 t, %1; cvt.u32.u64 %0, t; }" : "=r"(a) : "l"(ptr));
    return a;
}

// ---------------- mask dtype detection --------------------------------------
__global__ void detect_mask_kernel(const unsigned int* m) {
    if (threadIdx.x == 0 && blockIdx.x == 0) {
        int all01 = 1, allf = 1;
        for (int i = 0; i < 512; i++) {
            unsigned v = m[i];
            if (v > 1u) all01 = 0;
            if (v != 0u && v != 0x3F800000u) allf = 0;
        }
        g_mask_kind = all01 ? 0 : (allf ? 1 : 2);
    }
}

__device__ __forceinline__ bool mask_true(const void* m, int kind, int idx) {
    if (kind == 0) return ((const int*)m)[idx] != 0;
    if (kind == 1) return ((const float*)m)[idx] != 0.0f;
    return ((const unsigned char*)m)[idx] != 0;
}

// ---------------- fp32 -> fp16 convert ---------------------------------------
__global__ __launch_bounds__(256) void cvt_kernel(
    const float* __restrict__ x, __half* __restrict__ y, int n)
{
    int i = (blockIdx.x * 256 + threadIdx.x) * 8;
    if (i >= n) return;
    float4 a = *(const float4*)&x[i];
    float4 b = *(const float4*)&x[i + 4];
    __half h[8];
    h[0] = __float2half_rn(a.x); h[1] = __float2half_rn(a.y);
    h[2] = __float2half_rn(a.z); h[3] = __float2half_rn(a.w);
    h[4] = __float2half_rn(b.x); h[5] = __float2half_rn(b.y);
    h[6] = __float2half_rn(b.z); h[7] = __float2half_rn(b.w);
    *(uint4*)&y[i] = *(uint4*)h;
}

// ---------------- fp16 GEMM: C[2048,1024] = A @ W^T + bias -------------------
// BM=128 BN=128 BK=64; 256 thr; 8 warps (2M x 4N), warp 64x32 = 4x2 m16n16k16.
// cp.async double buffer; smem epilogue fuses bias and optional half output.
#define GEMM_SMEM 73728   // max(2*2*128*72 halfs = 73728B, 128*132 fp32 = 67584B)

__device__ __forceinline__ void gemm_load_chunk(
    unsigned int sA, unsigned int sW, int buf, int m0, int n0, int kc0, int tid,
    const __half* __restrict__ A, const __half* __restrict__ Wm)
{
    #pragma unroll
    for (int u = 0; u < 4; u++) {
        int f = tid + u * 256;
        int r = f >> 3, ch = f & 7;
        unsigned int off = (unsigned int)(buf * 128 * 72 + r * 72 + ch * 8) * 2;
        cp16(sA + off, A + (size_t)(m0 + r) * 1024 + kc0 + ch * 8);
        cp16(sW + off, Wm + (size_t)(n0 + r) * 1024 + kc0 + ch * 8);
    }
}

__global__ __launch_bounds__(256) void gemm_half(
    const __half* __restrict__ A, const __half* __restrict__ Wm,
    const float* __restrict__ bias, void* __restrict__ Cout, int out_is_half)
{
    extern __shared__ char smc[];
    __half* As = (__half*)smc;            // [2][128][72]
    __half* Ws = As + 2 * 128 * 72;       // [2][128][72]
    float*  Ss = (float*)smc;             // epilogue reuse [128][132]

    const int tid = threadIdx.x;
    const int w = tid >> 5;
    const int m0 = blockIdx.y * 128, n0 = blockIdx.x * 128;
    const int wm = w >> 2, wn = w & 3;

    const unsigned int sA = smem_u32(As);
    const unsigned int sW = smem_u32(Ws);

    wmma::fragment<wmma::accumulator, 16, 16, 16, float> c[4][2];
    #pragma unroll
    for (int i = 0; i < 4; i++)
        #pragma unroll
        for (int j = 0; j < 2; j++)
            wmma::fill_fragment(c[i][j], 0.0f);

    gemm_load_chunk(sA, sW, 0, m0, n0, 0,  tid, A, Wm); cp_commit();
    gemm_load_chunk(sA, sW, 1, m0, n0, 64, tid, A, Wm); cp_commit();

    for (int t = 0; t < 16; t++) {
        const int buf = t & 1;
        if (t == 15) asm volatile("cp.async.wait_group 0;" ::: "memory");
        else         asm volatile("cp.async.wait_group 1;" ::: "memory");
        __syncthreads();

        const __half* Ab = As + buf * 128 * 72;
        const __half* Wb = Ws + buf * 128 * 72;
        #pragma unroll
        for (int kk = 0; kk < 64; kk += 16) {
            wmma::fragment<wmma::matrix_a, 16, 16, 16, __half, wmma::row_major> a[4];
            wmma::fragment<wmma::matrix_b, 16, 16, 16, __half, wmma::col_major> bf[2];
            #pragma unroll
            for (int i = 0; i < 4; i++)
                wmma::load_matrix_sync(a[i], Ab + (wm * 64 + i * 16) * 72 + kk, 72);
            #pragma unroll
            for (int j = 0; j < 2; j++)
                wmma::load_matrix_sync(bf[j], Wb + (wn * 32 + j * 16) * 72 + kk, 72);
            #pragma unroll
            for (int i = 0; i < 4; i++)
                #pragma unroll
                for (int j = 0; j < 2; j++)
                    wmma::mma_sync(c[i][j], a[i], bf[j], c[i][j]);
        }
        __syncthreads();

        if (t + 2 < 16) {
            gemm_load_chunk(sA, sW, buf, m0, n0, (t + 2) * 64, tid, A, Wm);
            cp_commit();
        }
    }

    // epilogue: frags -> smem fp32, + bias, convert/store
    #pragma unroll
    for (int i = 0; i < 4; i++)
        #pragma unroll
        for (int j = 0; j < 2; j++)
            wmma::store_matrix_sync(&Ss[(wm * 64 + i * 16) * 132 + wn * 32 + j * 16],
                                    c[i][j], 132, wmma::mem_row_major);
    __syncthreads();

    if (out_is_half) {
        __half* C = (__half*)Cout;
        #pragma unroll
        for (int u = 0; u < 8; u++) {
            int f = tid + u * 256;
            int r = f >> 4, ch = f & 15;
            const float* src = &Ss[r * 132 + ch * 8];
            const float* bp = &bias[n0 + ch * 8];
            __half hv[8];
            #pragma unroll
            for (int e = 0; e < 8; e++) hv[e] = __float2half_rn(src[e] + bp[e]);
            *(uint4*)&C[(size_t)(m0 + r) * 1024 + n0 + ch * 8] = *(uint4*)hv;
        }
    } else {
        float* C = (float*)Cout;
        #pragma unroll
        for (int u = 0; u < 8; u++) {
            int f = tid + u * 256;
            int r = f >> 4, ch = f & 15;
            const float* src = &Ss[r * 132 + ch * 8];
            const float* bp = &bias[n0 + ch * 8];
            float ov[8];
            #pragma unroll
            for (int e = 0; e < 8; e++) ov[e] = src[e] + bp[e];
            *(float4*)&C[(size_t)(m0 + r) * 1024 + n0 + ch * 8] = *(float4*)ov;
            *(float4*)&C[(size_t)(m0 + r) * 1024 + n0 + ch * 8 + 4] = *(float4*)&ov[4];
        }
    }
}

// ---------------- scores: S = (Q*scale) Kh^T + bias/mask (fp16 MMA) ----------
#define SCORES_SMEM 67584   // max(2*128*72 halfs = 36864B, 128*132 fp32 = 67584B)

__global__ __launch_bounds__(256) void scores_half(
    const void* __restrict__ mask, const float* __restrict__ lb)
{
    extern __shared__ char smc[];
    __half* Qs = (__half*)smc;            // [128][72]
    __half* Ks = Qs + 128 * 72;           // [128][72]
    float*  Ss = (float*)smc;             // reuse [128][132]

    const int tid = threadIdx.x;
    const int w = tid >> 5;
    const int k0 = blockIdx.x * 128, q0 = blockIdx.y * 128;
    const int bh = blockIdx.z;
    const int b = bh >> 4, h = bh & 15;
    const int hc = h * DH_;
    const int wm = w >> 2, wn = w & 3;

    const __half2 sc2 = __float2half2_rn(0.125f);

    #pragma unroll
    for (int u = 0; u < 4; u++) {
        int f = tid + u * 256;
        int r = f >> 3, ch = f & 7;
        uint4 qv = *(const uint4*)&g_qh[(size_t)(b * LQ_ + q0 + r) * 1024 + hc + ch * 8];
        __half2* qp = (__half2*)&qv;
        #pragma unroll
        for (int e = 0; e < 4; e++) qp[e] = __hmul2(qp[e], sc2);
        *(uint4*)&Qs[r * 72 + ch * 8] = qv;
        *(uint4*)&Ks[r * 72 + ch * 8] =
            *(const uint4*)&g_kh[(size_t)(b * LK_ + k0 + r) * 1024 + hc + ch * 8];
    }
    __syncthreads();

    wmma::fragment<wmma::accumulator, 16, 16, 16, float> s[4][2];
    #pragma unroll
    for (int i = 0; i < 4; i++)
        #pragma unroll
        for (int j = 0; j < 2; j++)
            wmma::fill_fragment(s[i][j], 0.0f);

    #pragma unroll
    for (int kk = 0; kk < 64; kk += 16) {
        wmma::fragment<wmma::matrix_a, 16, 16, 16, __half, wmma::row_major> a[4];
        wmma::fragment<wmma::matrix_b, 16, 16, 16, __half, wmma::col_major> bf[2];
        #pragma unroll
        for (int i = 0; i < 4; i++)
            wmma::load_matrix_sync(a[i], Qs + (wm * 64 + i * 16) * 72 + kk, 72);
        #pragma unroll
        for (int j = 0; j < 2; j++)
            wmma::load_matrix_sync(bf[j], Ks + (wn * 32 + j * 16) * 72 + kk, 72);
        #pragma unroll
        for (int i = 0; i < 4; i++)
            #pragma unroll
            for (int j = 0; j < 2; j++)
                wmma::mma_sync(s[i][j], a[i], bf[j], s[i][j]);
    }
    __syncthreads();

    #pragma unroll
    for (int i = 0; i < 4; i++)
        #pragma unroll
        for (int j = 0; j < 2; j++)
            wmma::store_matrix_sync(&Ss[(wm * 64 + i * 16) * 132 + wn * 32 + j * 16],
                                    s[i][j], 132, wmma::mem_row_major);
    __syncthreads();

    const int kind = g_mask_kind;
    for (int i = tid * 4; i < 128 * 128; i += 1024) {
        int r = i >> 7, cc = i & 127;
        int q = q0 + r;
        float4 v = *(float4*)&Ss[r * 132 + cc];
        const float* lbrow = lb + (size_t)(b * LQ_ + q) * LK_ + k0 + cc;
        float o[4] = {v.x, v.y, v.z, v.w};
        #pragma unroll
        for (int e = 0; e < 4; e++) {
            bool mk = mask_true(mask, kind, b * LK_ + k0 + cc + e);
            o[e] += mk ? NEG_BIG : lbrow[e];
        }
        *(float4*)&g_s[((size_t)bh * LQ_ + q) * LK_ + k0 + cc] =
            make_float4(o[0], o[1], o[2], o[3]);
    }
}

// ---------------- row softmax over LK=1024, fp32 in -> half out --------------
__global__ __launch_bounds__(256) void softmax_kernel() {
    const size_t row = blockIdx.x;
    const float* s = &g_s[row * LK_];
    const int tid = threadIdx.x;
    const int lane = tid & 31, wid = tid >> 5;

    float4 v = *(const float4*)&s[tid * 4];
    float m = fmaxf(fmaxf(v.x, v.y), fmaxf(v.z, v.w));
    #pragma unroll
    for (int o = 16; o > 0; o >>= 1) m = fmaxf(m, __shfl_xor_sync(0xffffffffu, m, o));

    __shared__ float red[8], red2[8];
    if (lane == 0) red[wid] = m;
    __syncthreads();
    float bm = red[0];
    #pragma unroll
    for (int i = 1; i < 8; i++) bm = fmaxf(bm, red[i]);

    float e0 = __expf(v.x - bm), e1 = __expf(v.y - bm);
    float e2 = __expf(v.z - bm), e3 = __expf(v.w - bm);
    float sum = e0 + e1 + e2 + e3;
    #pragma unroll
    for (int o = 16; o > 0; o >>= 1) sum += __shfl_xor_sync(0xffffffffu, sum, o);
    if (lane == 0) red2[wid] = sum;
    __syncthreads();
    float tot = 0.0f;
    #pragma unroll
    for (int i = 0; i < 8; i++) tot += red2[i];

    float inv = 1.0f / tot;
    __half hv[4];
    hv[0] = __float2half_rn(e0 * inv); hv[1] = __float2half_rn(e1 * inv);
    hv[2] = __float2half_rn(e2 * inv); hv[3] = __float2half_rn(e3 * inv);
    *(uint2*)&g_ph[row * LK_ + tid * 4] = *(uint2*)hv;
}

// ---------------- PV: att = P @ Vh (fp16 MMA) --------------------------------
#define PV_SMEM (2 * 128 * 72 * 2 + 2 * 64 * 72 * 2)   // 55296 B

__global__ __launch_bounds__(256) void pv_half() {
    extern __shared__ char smc[];
    __half* Ps = (__half*)smc;            // [2][128][72]
    __half* Vs = Ps + 2 * 128 * 72;       // [2][64][72]

    const int tid = threadIdx.x;
    const int w = tid >> 5;
    const int m0 = blockIdx.x * 128;
    const int bh = blockIdx.y;
    const int b = bh >> 4, h = bh & 15;
    const int hc = h * DH_;
    const int wm = w >> 1, wn = w & 1;

    const unsigned int sP = smem_u32(Ps);
    const unsigned int sV = smem_u32(Vs);

    wmma::fragment<wmma::accumulator, 16, 16, 16, float> c[2][2];
    #pragma unroll
    for (int i = 0; i < 2; i++)
        #pragma unroll
        for (int j = 0; j < 2; j++)
            wmma::fill_fragment(c[i][j], 0.0f);

    // chunk loader: P 128x64, V 64x64 halfs
    #define PV_LOAD(buf, kc0)                                                          \
    {                                                                                  \
        _Pragma("unroll")                                                              \
        for (int u = 0; u < 4; u++) {                                                  \
            int f = tid + u * 256;                                                     \
            int r = f >> 3, ch = f & 7;                                                \
            cp16(sP + (unsigned)((buf) * 128 * 72 + r * 72 + ch * 8) * 2,              \
                 &g_ph[((size_t)bh * LQ_ + m0 + r) * 1024 + (kc0) + ch * 8]);          \
        }                                                                              \
        _Pragma("unroll")                                                              \
        for (int u = 0; u < 2; u++) {                                                  \
            int f = tid + u * 256;                                                     \
            int r = f >> 3, ch = f & 7;                                                \
            cp16(sV + (unsigned)((buf) * 64 * 72 + r * 72 + ch * 8) * 2,               \
                 &g_vh[(size_t)(b * LK_ + (kc0) + r) * 1024 + hc + ch * 8]);           \
        }                                                                              \
    }

    PV_LOAD(0, 0);  cp_commit();
    PV_LOAD(1, 64); cp_commit();

    for (int t = 0; t < 16; t++) {
        const int buf = t & 1;
        if (t == 15) asm volatile("cp.async.wait_group 0;" ::: "memory");
        else         asm volatile("cp.async.wait_group 1;" ::: "memory");
        __syncthreads();

        const __half* Pb = Ps + buf * 128 * 72;
        const __half* Vb = Vs + buf * 64 * 72;
        #pragma unroll
        for (int kk = 0; kk < 64; kk += 16) {
            wmma::fragment<wmma::matrix_a, 16, 16, 16, __half, wmma::row_major> a[2];
            wmma::fragment<wmma::matrix_b, 16, 16, 16, __half, wmma::row_major> bf[2];
            #pragma unroll
            for (int i = 0; i < 2; i++)
                wmma::load_matrix_sync(a[i], Pb + (wm * 32 + i * 16) * 72 + kk, 72);
            #pragma unroll
            for (int j = 0; j < 2; j++)
                wmma::load_matrix_sync(bf[j], Vb + kk * 72 + wn * 32 + j * 16, 72);
            #pragma unroll
            for (int i = 0; i < 2; i++)
                #pragma unroll
                for (int j = 0; j < 2; j++)
                    wmma::mma_sync(c[i][j], a[i], bf[j], c[i][j]);
        }
        __syncthreads();

        if (t + 2 < 16) {
            PV_LOAD(buf, (t + 2) * 64);
            cp_commit();
        }
    }

    #pragma unroll
    for (int i = 0; i < 2; i++)
        #pragma unroll
        for (int j = 0; j < 2; j++)
            wmma::store_matrix_sync(
                &g_att[(size_t)(b * LQ_ + m0 + wm * 32 + i * 16) * 1024 + hc + wn * 32 + j * 16],
                c[i][j], 1024, wmma::mem_row_major);
    #undef PV_LOAD
}

// ---------------- launch ------------------------------------------------------
extern "C" void kernel_launch(void* const* d_in, const int* in_sizes, int n_in,
                              void* d_out, int out_size)
{
    const float* q    = (const float*)d_in[0];
    const float* k    = (const float*)d_in[1];
    const float* v    = (const float*)d_in[2];
    const float* Wq   = (const float*)d_in[3];
    const float* bq   = (const float*)d_in[4];
    const float* Wk   = (const float*)d_in[5];
    const float* bk   = (const float*)d_in[6];
    const float* Wv   = (const float*)d_in[7];
    const float* bv   = (const float*)d_in[8];
    const float* Wo   = (const float*)d_in[9];
    const float* bo   = (const float*)d_in[10];
    const float* lb   = (const float*)d_in[11];
    const void*  mask = (const void*)d_in[12];
    float* out = (float*)d_out;

    __half *xh, *wh, *qh, *kh, *vh;
    float *att;
    cudaGetSymbolAddress((void**)&xh, g_xh);
    cudaGetSymbolAddress((void**)&wh, g_wh);
    cudaGetSymbolAddress((void**)&qh, g_qh);
    cudaGetSymbolAddress((void**)&kh, g_kh);
    cudaGetSymbolAddress((void**)&vh, g_vh);
    cudaGetSymbolAddress((void**)&att, g_att);

    cudaFuncSetAttribute(gemm_half,   cudaFuncAttributeMaxDynamicSharedMemorySize, GEMM_SMEM);
    cudaFuncSetAttribute(scores_half, cudaFuncAttributeMaxDynamicSharedMemorySize, SCORES_SMEM);
    cudaFuncSetAttribute(pv_half,     cudaFuncAttributeMaxDynamicSharedMemorySize, PV_SMEM);

    const int NACT = 2048 * 1024, NW = 1024 * 1024;
    dim3 ggemm(8, 16);   // N/128 x M/128

    detect_mask_kernel<<<1, 32>>>((const unsigned int*)mask);

    cvt_kernel<<<NACT / 2048, 256>>>(q, xh, NACT);
    cvt_kernel<<<NW / 2048, 256>>>(Wq, wh, NW);
    gemm_half<<<ggemm, 256, GEMM_SMEM>>>(xh, wh, bq, qh, 1);

    cvt_kernel<<<NACT / 2048, 256>>>(k, xh, NACT);
    cvt_kernel<<<NW / 2048, 256>>>(Wk, wh, NW);
    gemm_half<<<ggemm, 256, GEMM_SMEM>>>(xh, wh, bk, kh, 1);

    cvt_kernel<<<NACT / 2048, 256>>>(v, xh, NACT);
    cvt_kernel<<<NW / 2048, 256>>>(Wv, wh, NW);
    gemm_half<<<ggemm, 256, GEMM_SMEM>>>(xh, wh, bv, vh, 1);

    scores_half<<<dim3(8, 8, BH_), 256, SCORES_SMEM>>>(mask, lb);
    softmax_kernel<<<BH_ * LQ_, 256>>>();
    pv_half<<<dim3(8, BH_), 256, PV_SMEM>>>();

    cvt_kernel<<<NACT / 2048, 256>>>(att, xh, NACT);
    cvt_kernel<<<NW / 2048, 256>>>(Wo, wh, NW);
    gemm_half<<<ggemm, 256, GEMM_SMEM>>>(xh, wh, bo, out, 0);
}

// round 11
// speedup vs baseline: 2.4381x; 1.0639x over previous
#include <cuda_runtime.h>
#include <cuda_fp16.h>
#include <mma.h>
#include <math.h>
#include <cstdint>

using namespace nvcuda;

#define B_   2
#define LQ_  1024
#define LK_  1024
#define D_   1024
#define H_   16
#define DH_  64
#define BH_  (B_ * H_)
#define NEG_BIG (-3.402823466e38f)

// ---------------- scratch ----------------------------------------------------
__device__ __half g_xh[2048 * 1024];              // GEMM A staging (half)
__device__ __half g_wh[1024 * 1024];              // weight staging (half)
__device__ __half g_qh[2048 * 1024];              // projected Q (half)
__device__ __half g_kh[2048 * 1024];              // projected K (half)
__device__ __half g_vh[2048 * 1024];              // projected V (half)
__device__ int    g_mask_kind;

// ---------------- helpers -----------------------------------------------------
__device__ __forceinline__ void cp16(unsigned int dst, const void* src) {
    asm volatile("cp.async.cg.shared.global [%0], [%1], 16;\n" :: "r"(dst), "l"(src));
}
__device__ __forceinline__ void cp_commit() {
    asm volatile("cp.async.commit_group;\n" ::: "memory");
}
__device__ __forceinline__ unsigned int smem_u32(const void* ptr) {
    unsigned int a;
    asm("{ .reg .u64 t; cvta.to.shared.u64 t, %1; cvt.u32.u64 %0, t; }" : "=r"(a) : "l"(ptr));
    return a;
}

// ---------------- mask dtype detection --------------------------------------
__global__ void detect_mask_kernel(const unsigned int* m) {
    if (threadIdx.x == 0 && blockIdx.x == 0) {
        int all01 = 1, allf = 1;
        for (int i = 0; i < 512; i++) {
            unsigned v = m[i];
            if (v > 1u) all01 = 0;
            if (v != 0u && v != 0x3F800000u) allf = 0;
        }
        g_mask_kind = all01 ? 0 : (allf ? 1 : 2);
    }
}

__device__ __forceinline__ bool mask_true(const void* m, int kind, int idx) {
    if (kind == 0) return ((const int*)m)[idx] != 0;
    if (kind == 1) return ((const float*)m)[idx] != 0.0f;
    return ((const unsigned char*)m)[idx] != 0;
}

// ---------------- fp32 -> fp16 convert ---------------------------------------
__global__ __launch_bounds__(256) void cvt_kernel(
    const float* __restrict__ x, __half* __restrict__ y, int n)
{
    int i = (blockIdx.x * 256 + threadIdx.x) * 8;
    if (i >= n) return;
    float4 a = *(const float4*)&x[i];
    float4 b = *(const float4*)&x[i + 4];
    __half h[8];
    h[0] = __float2half_rn(a.x); h[1] = __float2half_rn(a.y);
    h[2] = __float2half_rn(a.z); h[3] = __float2half_rn(a.w);
    h[4] = __float2half_rn(b.x); h[5] = __float2half_rn(b.y);
    h[6] = __float2half_rn(b.z); h[7] = __float2half_rn(b.w);
    *(uint4*)&y[i] = *(uint4*)h;
}

// ---------------- fp16 GEMM: C[2048,1024] = A @ W^T + bias -------------------
#define GEMM_SMEM 73728

__device__ __forceinline__ void gemm_load_chunk(
    unsigned int sA, unsigned int sW, int buf, int m0, int n0, int kc0, int tid,
    const __half* __restrict__ A, const __half* __restrict__ Wm)
{
    #pragma unroll
    for (int u = 0; u < 4; u++) {
        int f = tid + u * 256;
        int r = f >> 3, ch = f & 7;
        unsigned int off = (unsigned int)(buf * 128 * 72 + r * 72 + ch * 8) * 2;
        cp16(sA + off, A + (size_t)(m0 + r) * 1024 + kc0 + ch * 8);
        cp16(sW + off, Wm + (size_t)(n0 + r) * 1024 + kc0 + ch * 8);
    }
}

__global__ __launch_bounds__(256) void gemm_half(
    const __half* __restrict__ A, const __half* __restrict__ Wm,
    const float* __restrict__ bias, void* __restrict__ Cout, int out_is_half)
{
    extern __shared__ char smc[];
    __half* As = (__half*)smc;
    __half* Ws = As + 2 * 128 * 72;
    float*  Ss = (float*)smc;

    const int tid = threadIdx.x;
    const int w = tid >> 5;
    const int m0 = blockIdx.y * 128, n0 = blockIdx.x * 128;
    const int wm = w >> 2, wn = w & 3;

    const unsigned int sA = smem_u32(As);
    const unsigned int sW = smem_u32(Ws);

    wmma::fragment<wmma::accumulator, 16, 16, 16, float> c[4][2];
    #pragma unroll
    for (int i = 0; i < 4; i++)
        #pragma unroll
        for (int j = 0; j < 2; j++)
            wmma::fill_fragment(c[i][j], 0.0f);

    gemm_load_chunk(sA, sW, 0, m0, n0, 0,  tid, A, Wm); cp_commit();
    gemm_load_chunk(sA, sW, 1, m0, n0, 64, tid, A, Wm); cp_commit();

    for (int t = 0; t < 16; t++) {
        const int buf = t & 1;
        if (t == 15) asm volatile("cp.async.wait_group 0;" ::: "memory");
        else         asm volatile("cp.async.wait_group 1;" ::: "memory");
        __syncthreads();

        const __half* Ab = As + buf * 128 * 72;
        const __half* Wb = Ws + buf * 128 * 72;
        #pragma unroll
        for (int kk = 0; kk < 64; kk += 16) {
            wmma::fragment<wmma::matrix_a, 16, 16, 16, __half, wmma::row_major> a[4];
            wmma::fragment<wmma::matrix_b, 16, 16, 16, __half, wmma::col_major> bf[2];
            #pragma unroll
            for (int i = 0; i < 4; i++)
                wmma::load_matrix_sync(a[i], Ab + (wm * 64 + i * 16) * 72 + kk, 72);
            #pragma unroll
            for (int j = 0; j < 2; j++)
                wmma::load_matrix_sync(bf[j], Wb + (wn * 32 + j * 16) * 72 + kk, 72);
            #pragma unroll
            for (int i = 0; i < 4; i++)
                #pragma unroll
                for (int j = 0; j < 2; j++)
                    wmma::mma_sync(c[i][j], a[i], bf[j], c[i][j]);
        }
        __syncthreads();

        if (t + 2 < 16) {
            gemm_load_chunk(sA, sW, buf, m0, n0, (t + 2) * 64, tid, A, Wm);
            cp_commit();
        }
    }

    #pragma unroll
    for (int i = 0; i < 4; i++)
        #pragma unroll
        for (int j = 0; j < 2; j++)
            wmma::store_matrix_sync(&Ss[(wm * 64 + i * 16) * 132 + wn * 32 + j * 16],
                                    c[i][j], 132, wmma::mem_row_major);
    __syncthreads();

    if (out_is_half) {
        __half* C = (__half*)Cout;
        #pragma unroll
        for (int u = 0; u < 8; u++) {
            int f = tid + u * 256;
            int r = f >> 4, ch = f & 15;
            const float* src = &Ss[r * 132 + ch * 8];
            const float* bp = &bias[n0 + ch * 8];
            __half hv[8];
            #pragma unroll
            for (int e = 0; e < 8; e++) hv[e] = __float2half_rn(src[e] + bp[e]);
            *(uint4*)&C[(size_t)(m0 + r) * 1024 + n0 + ch * 8] = *(uint4*)hv;
        }
    } else {
        float* C = (float*)Cout;
        #pragma unroll
        for (int u = 0; u < 8; u++) {
            int f = tid + u * 256;
            int r = f >> 4, ch = f & 15;
            const float* src = &Ss[r * 132 + ch * 8];
            const float* bp = &bias[n0 + ch * 8];
            float ov[8];
            #pragma unroll
            for (int e = 0; e < 8; e++) ov[e] = src[e] + bp[e];
            *(float4*)&C[(size_t)(m0 + r) * 1024 + n0 + ch * 8] = *(float4*)ov;
            *(float4*)&C[(size_t)(m0 + r) * 1024 + n0 + ch * 8 + 4] = *(float4*)&ov[4];
        }
    }
}

// ---------------- flash attention: online softmax, 64q x 64k tiles -----------
// smem: Qs[64][72]h Ks[2][64][72]h Vs[2][64][72]h Ps[64][72]h Ss[64][68]f
//       Os[64][68]f m/l/alpha[64]f   => 90880 B, 2 CTA/SM
#define FLASH_SMEM 90880

__global__ __launch_bounds__(256, 2) void flash_attn(
    const void* __restrict__ mask, const float* __restrict__ lb,
    __half* __restrict__ outh)
{
    extern __shared__ char smc[];
    __half* Qs = (__half*)smc;                 // [64][72]
    __half* Ks = Qs + 64 * 72;                 // [2][64][72]
    __half* Vs = Ks + 2 * 64 * 72;             // [2][64][72]
    __half* Ps = Vs + 2 * 64 * 72;             // [64][72]
    float*  Ss = (float*)(Ps + 64 * 72);       // [64][68]
    float*  Os = Ss + 64 * 68;                 // [64][68]
    float*  m_s = Os + 64 * 68;                // [64]
    float*  l_s = m_s + 64;                    // [64]
    float*  a_s = l_s + 64;                    // [64]

    const int tid = threadIdx.x;
    const int w = tid >> 5;
    const int q0 = blockIdx.x * 64;
    const int bh = blockIdx.y;
    const int b = bh >> 4, h = bh & 15;
    const int hc = h * DH_;
    const int kind = g_mask_kind;

    const unsigned int sK = smem_u32(Ks);
    const unsigned int sV = smem_u32(Vs);

    // load Q (x 0.125), zero O, init stats
    const __half2 sc2 = __float2half2_rn(0.125f);
    #pragma unroll
    for (int u = 0; u < 2; u++) {
        int f = tid + u * 256;
        int r = f >> 3, ch = f & 7;
        uint4 qv = *(const uint4*)&g_qh[(size_t)(b * LQ_ + q0 + r) * 1024 + hc + ch * 8];
        __half2* qp = (__half2*)&qv;
        #pragma unroll
        for (int e = 0; e < 4; e++) qp[e] = __hmul2(qp[e], sc2);
        *(uint4*)&Qs[r * 72 + ch * 8] = qv;
    }
    for (int i = tid; i < 64 * 68; i += 256) Os[i] = 0.0f;
    if (tid < 64) { m_s[tid] = -INFINITY; l_s[tid] = 0.0f; }

    #define KV_LOAD(buf, kc0)                                                        \
    {                                                                                \
        _Pragma("unroll")                                                            \
        for (int u = 0; u < 2; u++) {                                                \
            int f = tid + u * 256;                                                   \
            int r = f >> 3, ch = f & 7;                                              \
            unsigned int off = (unsigned)((buf) * 64 * 72 + r * 72 + ch * 8) * 2;    \
            size_t g = (size_t)(b * LK_ + (kc0) + r) * 1024 + hc + ch * 8;           \
            cp16(sK + off, &g_kh[g]);                                                \
            cp16(sV + off, &g_vh[g]);                                                \
        }                                                                            \
    }

    KV_LOAD(0, 0); cp_commit();

    const int rr = tid >> 2, qr = tid & 3;    // softmax mapping: row, 16-col quarter

    for (int t = 0; t < 16; t++) {
        const int buf = t & 1;
        asm volatile("cp.async.wait_group 0;" ::: "memory");
        __syncthreads();
        if (t + 1 < 16) { KV_LOAD(buf ^ 1, (t + 1) * 64); cp_commit(); }

        // ---- S = Q K^T (64x64): warp w -> rows (w>>2)*32, cols (w&3)*16
        {
            const int wm = w >> 2, wn = w & 3;
            const __half* Kb = Ks + buf * 64 * 72;
            wmma::fragment<wmma::accumulator, 16, 16, 16, float> s[2];
            wmma::fill_fragment(s[0], 0.0f);
            wmma::fill_fragment(s[1], 0.0f);
            #pragma unroll
            for (int kk = 0; kk < 64; kk += 16) {
                wmma::fragment<wmma::matrix_a, 16, 16, 16, __half, wmma::row_major> a[2];
                wmma::fragment<wmma::matrix_b, 16, 16, 16, __half, wmma::col_major> bf;
                #pragma unroll
                for (int i = 0; i < 2; i++)
                    wmma::load_matrix_sync(a[i], Qs + (wm * 32 + i * 16) * 72 + kk, 72);
                wmma::load_matrix_sync(bf, Kb + (wn * 16) * 72 + kk, 72);
                #pragma unroll
                for (int i = 0; i < 2; i++)
                    wmma::mma_sync(s[i], a[i], bf, s[i]);
            }
            #pragma unroll
            for (int i = 0; i < 2; i++)
                wmma::store_matrix_sync(&Ss[(wm * 32 + i * 16) * 68 + wn * 16],
                                        s[i], 68, wmma::mem_row_major);
        }
        __syncthreads();

        // ---- online softmax: thread handles row rr, cols qr*16..+15
        {
            const int q = q0 + rr;
            const int kbase = t * 64 + qr * 16;
            const float* lbrow = lb + (size_t)(b * LQ_ + q) * LK_ + kbase;
            float vals[16];
            float mx = -INFINITY;
            #pragma unroll
            for (int j = 0; j < 16; j += 4) {
                float4 sv = *(float4*)&Ss[rr * 68 + qr * 16 + j];
                float4 bv = *(const float4*)&lbrow[j];
                float o[4] = {sv.x + (mask_true(mask, kind, b * LK_ + kbase + j + 0) ? NEG_BIG : bv.x),
                              sv.y + (mask_true(mask, kind, b * LK_ + kbase + j + 1) ? NEG_BIG : bv.y),
                              sv.z + (mask_true(mask, kind, b * LK_ + kbase + j + 2) ? NEG_BIG : bv.z),
                              sv.w + (mask_true(mask, kind, b * LK_ + kbase + j + 3) ? NEG_BIG : bv.w)};
                #pragma unroll
                for (int e = 0; e < 4; e++) { vals[j + e] = o[e]; mx = fmaxf(mx, o[e]); }
            }
            mx = fmaxf(mx, __shfl_xor_sync(0xffffffffu, mx, 1));
            mx = fmaxf(mx, __shfl_xor_sync(0xffffffffu, mx, 2));
            const float mold = m_s[rr];
            const float mnew = fmaxf(mold, mx);
            float sum = 0.0f;
            #pragma unroll
            for (int j = 0; j < 16; j += 2) {
                float p0 = __expf(vals[j] - mnew);
                float p1 = __expf(vals[j + 1] - mnew);
                sum += p0 + p1;
                *(__half2*)&Ps[rr * 72 + qr * 16 + j] = __floats2half2_rn(p0, p1);
            }
            sum += __shfl_xor_sync(0xffffffffu, sum, 1);
            sum += __shfl_xor_sync(0xffffffffu, sum, 2);
            if (qr == 0) {
                float alpha = __expf(mold - mnew);
                l_s[rr] = l_s[rr] * alpha + sum;
                m_s[rr] = mnew;
                a_s[rr] = alpha;
            }
        }
        __syncthreads();

        // ---- scale O rows by alpha
        {
            const float alpha = a_s[rr];
            float* orow = &Os[rr * 68 + qr * 16];
            #pragma unroll
            for (int j = 0; j < 16; j += 4) {
                float4 ov = *(float4*)&orow[j];
                ov.x *= alpha; ov.y *= alpha; ov.z *= alpha; ov.w *= alpha;
                *(float4*)&orow[j] = ov;
            }
        }
        __syncthreads();

        // ---- O += P V : warp w -> rows (w>>1)*16, cols (w&1)*32 (2 frags)
        {
            const int wm = w >> 1, wn = w & 1;
            const __half* Vb = Vs + buf * 64 * 72;
            wmma::fragment<wmma::accumulator, 16, 16, 16, float> c[2];
            #pragma unroll
            for (int j = 0; j < 2; j++)
                wmma::load_matrix_sync(c[j], &Os[(wm * 16) * 68 + wn * 32 + j * 16],
                                       68, wmma::mem_row_major);
            #pragma unroll
            for (int kk = 0; kk < 64; kk += 16) {
                wmma::fragment<wmma::matrix_a, 16, 16, 16, __half, wmma::row_major> a;
                wmma::fragment<wmma::matrix_b, 16, 16, 16, __half, wmma::row_major> bf[2];
                wmma::load_matrix_sync(a, Ps + (wm * 16) * 72 + kk, 72);
                #pragma unroll
                for (int j = 0; j < 2; j++)
                    wmma::load_matrix_sync(bf[j], Vb + kk * 72 + wn * 32 + j * 16, 72);
                #pragma unroll
                for (int j = 0; j < 2; j++)
                    wmma::mma_sync(c[j], a, bf[j], c[j]);
            }
            #pragma unroll
            for (int j = 0; j < 2; j++)
                wmma::store_matrix_sync(&Os[(wm * 16) * 68 + wn * 32 + j * 16],
                                        c[j], 68, wmma::mem_row_major);
        }
    }
    #undef KV_LOAD

    __syncthreads();
    // ---- normalize and write half output
    {
        const float inv = 1.0f / l_s[rr];
        const float* orow = &Os[rr * 68 + qr * 16];
        __half hv[16];
        #pragma unroll
        for (int j = 0; j < 16; j++) hv[j] = __float2half_rn(orow[j] * inv);
        __half* dst = &outh[(size_t)(b * LQ_ + q0 + rr) * 1024 + hc + qr * 16];
        *(uint4*)&dst[0] = *(uint4*)&hv[0];
        *(uint4*)&dst[8] = *(uint4*)&hv[8];
    }
}

// ---------------- launch ------------------------------------------------------
extern "C" void kernel_launch(void* const* d_in, const int* in_sizes, int n_in,
                              void* d_out, int out_size)
{
    const float* q    = (const float*)d_in[0];
    const float* k    = (const float*)d_in[1];
    const float* v    = (const float*)d_in[2];
    const float* Wq   = (const float*)d_in[3];
    const float* bq   = (const float*)d_in[4];
    const float* Wk   = (const float*)d_in[5];
    const float* bk   = (const float*)d_in[6];
    const float* Wv   = (const float*)d_in[7];
    const float* bv   = (const float*)d_in[8];
    const float* Wo   = (const float*)d_in[9];
    const float* bo   = (const float*)d_in[10];
    const float* lb   = (const float*)d_in[11];
    const void*  mask = (const void*)d_in[12];
    float* out = (float*)d_out;

    __half *xh, *wh, *qh, *kh, *vh;
    cudaGetSymbolAddress((void**)&xh, g_xh);
    cudaGetSymbolAddress((void**)&wh, g_wh);
    cudaGetSymbolAddress((void**)&qh, g_qh);
    cudaGetSymbolAddress((void**)&kh, g_kh);
    cudaGetSymbolAddress((void**)&vh, g_vh);

    cudaFuncSetAttribute(gemm_half,  cudaFuncAttributeMaxDynamicSharedMemorySize, GEMM_SMEM);
    cudaFuncSetAttribute(flash_attn, cudaFuncAttributeMaxDynamicSharedMemorySize, FLASH_SMEM);

    const int NACT = 2048 * 1024, NW = 1024 * 1024;
    dim3 ggemm(8, 16);   // N/128 x M/128

    detect_mask_kernel<<<1, 32>>>((const unsigned int*)mask);

    cvt_kernel<<<NACT / 2048, 256>>>(q, xh, NACT);
    cvt_kernel<<<NW / 2048, 256>>>(Wq, wh, NW);
    gemm_half<<<ggemm, 256, GEMM_SMEM>>>(xh, wh, bq, qh, 1);

    cvt_kernel<<<NACT / 2048, 256>>>(k, xh, NACT);
    cvt_kernel<<<NW / 2048, 256>>>(Wk, wh, NW);
    gemm_half<<<ggemm, 256, GEMM_SMEM>>>(xh, wh, bk, kh, 1);

    cvt_kernel<<<NACT / 2048, 256>>>(v, xh, NACT);
    cvt_kernel<<<NW / 2048, 256>>>(Wv, wh, NW);
    gemm_half<<<ggemm, 256, GEMM_SMEM>>>(xh, wh, bv, vh, 1);

    // fused attention -> half att directly into GEMM staging buffer
    flash_attn<<<dim3(LQ_ / 64, BH_), 256, FLASH_SMEM>>>(mask, lb, xh);

    cvt_kernel<<<NW / 2048, 256>>>(Wo, wh, NW);
    gemm_half<<<ggemm, 256, GEMM_SMEM>>>(xh, wh, bo, out, 0);
}

// round 12
// speedup vs baseline: 2.6210x; 1.0750x over previous
#include <cuda_runtime.h>
#include <cuda_fp16.h>
#include <mma.h>
#include <math.h>
#include <cstdint>

using namespace nvcuda;

#define B_   2
#define LQ_  1024
#define LK_  1024
#define D_   1024
#define H_   16
#define DH_  64
#define BH_  (B_ * H_)
#define NEG_BIG (-3.402823466e38f)

// ---------------- scratch ----------------------------------------------------
__device__ __half g_xh3[3 * 2048 * 1024];         // staged inputs q/k/v (half); slot0 reused for att
__device__ __half g_wh4[4 * 1024 * 1024];         // staged weights Wq/Wk/Wv/Wo (half)
__device__ __half g_qh[2048 * 1024];              // projected Q (half)
__device__ __half g_kh[2048 * 1024];              // projected K (half)
__device__ __half g_vh[2048 * 1024];              // projected V (half)
__device__ int    g_mask_kind;

// ---------------- helpers -----------------------------------------------------
__device__ __forceinline__ void cp16(unsigned int dst, const void* src) {
    asm volatile("cp.async.cg.shared.global [%0], [%1], 16;\n" :: "r"(dst), "l"(src));
}
__device__ __forceinline__ void cp_commit() {
    asm volatile("cp.async.commit_group;\n" ::: "memory");
}
__device__ __forceinline__ unsigned int smem_u32(const void* ptr) {
    unsigned int a;
    asm("{ .reg .u64 t; cvta.to.shared.u64 t, %1; cvt.u32.u64 %0, t; }" : "=r"(a) : "l"(ptr));
    return a;
}

// ---------------- mask dtype detection --------------------------------------
__global__ void detect_mask_kernel(const unsigned int* m) {
    if (threadIdx.x == 0 && blockIdx.x == 0) {
        int all01 = 1, allf = 1;
        for (int i = 0; i < 512; i++) {
            unsigned v = m[i];
            if (v > 1u) all01 = 0;
            if (v != 0u && v != 0x3F800000u) allf = 0;
        }
        g_mask_kind = all01 ? 0 : (allf ? 1 : 2);
    }
}

__device__ __forceinline__ bool mask_true(const void* m, int kind, int idx) {
    if (kind == 0) return ((const int*)m)[idx] != 0;
    if (kind == 1) return ((const float*)m)[idx] != 0.0f;
    return ((const unsigned char*)m)[idx] != 0;
}

// ---------------- fp32 -> fp16 converts (batched) -----------------------------
__device__ __forceinline__ void cvt8(const float* __restrict__ x, __half* __restrict__ y, int i) {
    float4 a = *(const float4*)&x[i];
    float4 b = *(const float4*)&x[i + 4];
    __half h[8];
    h[0] = __float2half_rn(a.x); h[1] = __float2half_rn(a.y);
    h[2] = __float2half_rn(a.z); h[3] = __float2half_rn(a.w);
    h[4] = __float2half_rn(b.x); h[5] = __float2half_rn(b.y);
    h[6] = __float2half_rn(b.z); h[7] = __float2half_rn(b.w);
    *(uint4*)&y[i] = *(uint4*)h;
}

__global__ __launch_bounds__(256) void cvt_qkv(
    const float* __restrict__ x0, const float* __restrict__ x1,
    const float* __restrict__ x2, __half* __restrict__ y)
{
    const int z = blockIdx.z;
    const float* x = (z == 0) ? x0 : (z == 1) ? x1 : x2;
    cvt8(x, y + (size_t)z * 2048 * 1024, (blockIdx.x * 256 + threadIdx.x) * 8);
}

__global__ __launch_bounds__(256) void cvt_w4(
    const float* __restrict__ w0, const float* __restrict__ w1,
    const float* __restrict__ w2, const float* __restrict__ w3,
    __half* __restrict__ y)
{
    const int z = blockIdx.z;
    const float* x = (z == 0) ? w0 : (z == 1) ? w1 : (z == 2) ? w2 : w3;
    cvt8(x, y + (size_t)z * 1024 * 1024, (blockIdx.x * 256 + threadIdx.x) * 8);
}

// ---------------- fp16 GEMM core: C[2048,1024] = A @ W^T + bias --------------
#define GEMM_SMEM 73728

__device__ __forceinline__ void gemm_load_chunk(
    unsigned int sA, unsigned int sW, int buf, int m0, int n0, int kc0, int tid,
    const __half* __restrict__ A, const __half* __restrict__ Wm)
{
    #pragma unroll
    for (int u = 0; u < 4; u++) {
        int f = tid + u * 256;
        int r = f >> 3, ch = f & 7;
        unsigned int off = (unsigned int)(buf * 128 * 72 + r * 72 + ch * 8) * 2;
        cp16(sA + off, A + (size_t)(m0 + r) * 1024 + kc0 + ch * 8);
        cp16(sW + off, Wm + (size_t)(n0 + r) * 1024 + kc0 + ch * 8);
    }
}

__device__ __forceinline__ void gemm_core(
    char* smc, const __half* __restrict__ A, const __half* __restrict__ Wm,
    const float* __restrict__ bias, void* __restrict__ Cout, int out_is_half)
{
    __half* As = (__half*)smc;
    __half* Ws = As + 2 * 128 * 72;
    float*  Ss = (float*)smc;

    const int tid = threadIdx.x;
    const int w = tid >> 5;
    const int m0 = blockIdx.y * 128, n0 = blockIdx.x * 128;
    const int wm = w >> 2, wn = w & 3;

    const unsigned int sA = smem_u32(As);
    const unsigned int sW = smem_u32(Ws);

    wmma::fragment<wmma::accumulator, 16, 16, 16, float> c[4][2];
    #pragma unroll
    for (int i = 0; i < 4; i++)
        #pragma unroll
        for (int j = 0; j < 2; j++)
            wmma::fill_fragment(c[i][j], 0.0f);

    gemm_load_chunk(sA, sW, 0, m0, n0, 0,  tid, A, Wm); cp_commit();
    gemm_load_chunk(sA, sW, 1, m0, n0, 64, tid, A, Wm); cp_commit();

    for (int t = 0; t < 16; t++) {
        const int buf = t & 1;
        if (t == 15) asm volatile("cp.async.wait_group 0;" ::: "memory");
        else         asm volatile("cp.async.wait_group 1;" ::: "memory");
        __syncthreads();

        const __half* Ab = As + buf * 128 * 72;
        const __half* Wb = Ws + buf * 128 * 72;
        #pragma unroll
        for (int kk = 0; kk < 64; kk += 16) {
            wmma::fragment<wmma::matrix_a, 16, 16, 16, __half, wmma::row_major> a[4];
            wmma::fragment<wmma::matrix_b, 16, 16, 16, __half, wmma::col_major> bf[2];
            #pragma unroll
            for (int i = 0; i < 4; i++)
                wmma::load_matrix_sync(a[i], Ab + (wm * 64 + i * 16) * 72 + kk, 72);
            #pragma unroll
            for (int j = 0; j < 2; j++)
                wmma::load_matrix_sync(bf[j], Wb + (wn * 32 + j * 16) * 72 + kk, 72);
            #pragma unroll
            for (int i = 0; i < 4; i++)
                #pragma unroll
                for (int j = 0; j < 2; j++)
                    wmma::mma_sync(c[i][j], a[i], bf[j], c[i][j]);
        }
        __syncthreads();

        if (t + 2 < 16) {
            gemm_load_chunk(sA, sW, buf, m0, n0, (t + 2) * 64, tid, A, Wm);
            cp_commit();
        }
    }

    #pragma unroll
    for (int i = 0; i < 4; i++)
        #pragma unroll
        for (int j = 0; j < 2; j++)
            wmma::store_matrix_sync(&Ss[(wm * 64 + i * 16) * 132 + wn * 32 + j * 16],
                                    c[i][j], 132, wmma::mem_row_major);
    __syncthreads();

    if (out_is_half) {
        __half* C = (__half*)Cout;
        #pragma unroll
        for (int u = 0; u < 8; u++) {
            int f = tid + u * 256;
            int r = f >> 4, ch = f & 15;
            const float* src = &Ss[r * 132 + ch * 8];
            const float* bp = &bias[n0 + ch * 8];
            __half hv[8];
            #pragma unroll
            for (int e = 0; e < 8; e++) hv[e] = __float2half_rn(src[e] + bp[e]);
            *(uint4*)&C[(size_t)(m0 + r) * 1024 + n0 + ch * 8] = *(uint4*)hv;
        }
    } else {
        float* C = (float*)Cout;
        #pragma unroll
        for (int u = 0; u < 8; u++) {
            int f = tid + u * 256;
            int r = f >> 4, ch = f & 15;
            const float* src = &Ss[r * 132 + ch * 8];
            const float* bp = &bias[n0 + ch * 8];
            float ov[8];
            #pragma unroll
            for (int e = 0; e < 8; e++) ov[e] = src[e] + bp[e];
            *(float4*)&C[(size_t)(m0 + r) * 1024 + n0 + ch * 8] = *(float4*)ov;
            *(float4*)&C[(size_t)(m0 + r) * 1024 + n0 + ch * 8 + 4] = *(float4*)&ov[4];
        }
    }
}

// batched Q/K/V projection: grid (8,16,3)
__global__ __launch_bounds__(256) void gemm_qkv(
    const __half* __restrict__ Abase, const __half* __restrict__ Wbase,
    const float* __restrict__ b0, const float* __restrict__ b1, const float* __restrict__ b2,
    __half* __restrict__ C0, __half* __restrict__ C1, __half* __restrict__ C2)
{
    extern __shared__ char smc[];
    const int z = blockIdx.z;
    const float* bias = (z == 0) ? b0 : (z == 1) ? b1 : b2;
    __half* C = (z == 0) ? C0 : (z == 1) ? C1 : C2;
    gemm_core(smc, Abase + (size_t)z * 2048 * 1024,
              Wbase + (size_t)z * 1024 * 1024, bias, C, 1);
}

__global__ __launch_bounds__(256) void gemm_out(
    const __half* __restrict__ A, const __half* __restrict__ Wm,
    const float* __restrict__ bias, float* __restrict__ C)
{
    extern __shared__ char smc[];
    gemm_core(smc, A, Wm, bias, C, 0);
}

// ---------------- flash attention: online softmax, 64q x 64k tiles -----------
// smem: Qs[64][72]h Ks[2][64][72]h Vs[2][64][72]h Ps[64][72]h Ss[64][68]f
//       Os[64][68]f m/l[64]f   => ~90.6 KB, 2 CTA/SM. 3 barriers per k-tile.
#define FLASH_SMEM 90624

__global__ __launch_bounds__(256, 2) void flash_attn(
    const void* __restrict__ mask, const float* __restrict__ lb,
    __half* __restrict__ outh)
{
    extern __shared__ char smc[];
    __half* Qs = (__half*)smc;                 // [64][72]
    __half* Ks = Qs + 64 * 72;                 // [2][64][72]
    __half* Vs = Ks + 2 * 64 * 72;             // [2][64][72]
    __half* Ps = Vs + 2 * 64 * 72;             // [64][72]
    float*  Ss = (float*)(Ps + 64 * 72);       // [64][68]
    float*  Os = Ss + 64 * 68;                 // [64][68]
    float*  m_s = Os + 64 * 68;                // [64]
    float*  l_s = m_s + 64;                    // [64]

    const int tid = threadIdx.x;
    const int w = tid >> 5;
    const int lane = tid & 31;
    const int q0 = blockIdx.x * 64;
    const int bh = blockIdx.y;
    const int b = bh >> 4, h = bh & 15;
    const int hc = h * DH_;
    const int kind = g_mask_kind;

    const unsigned int sK = smem_u32(Ks);
    const unsigned int sV = smem_u32(Vs);

    // load Q (x 0.125), zero O, init stats
    const __half2 sc2 = __float2half2_rn(0.125f);
    #pragma unroll
    for (int u = 0; u < 2; u++) {
        int f = tid + u * 256;
        int r = f >> 3, ch = f & 7;
        uint4 qv = *(const uint4*)&g_qh[(size_t)(b * LQ_ + q0 + r) * 1024 + hc + ch * 8];
        __half2* qp = (__half2*)&qv;
        #pragma unroll
        for (int e = 0; e < 4; e++) qp[e] = __hmul2(qp[e], sc2);
        *(uint4*)&Qs[r * 72 + ch * 8] = qv;
    }
    for (int i = tid; i < 64 * 68; i += 256) Os[i] = 0.0f;
    if (tid < 64) { m_s[tid] = -INFINITY; l_s[tid] = 0.0f; }

    #define KV_LOAD(buf, kc0)                                                        \
    {                                                                                \
        _Pragma("unroll")                                                            \
        for (int u = 0; u < 2; u++) {                                                \
            int f = tid + u * 256;                                                   \
            int r = f >> 3, ch = f & 7;                                              \
            unsigned int off = (unsigned)((buf) * 64 * 72 + r * 72 + ch * 8) * 2;    \
            size_t g = (size_t)(b * LK_ + (kc0) + r) * 1024 + hc + ch * 8;           \
            cp16(sK + off, &g_kh[g]);                                                \
            cp16(sV + off, &g_vh[g]);                                                \
        }                                                                            \
    }

    KV_LOAD(0, 0); cp_commit();

    const int rr = tid >> 2, qr = tid & 3;    // softmax mapping: row, 16-col quarter

    for (int t = 0; t < 16; t++) {
        const int buf = t & 1;
        asm volatile("cp.async.wait_group 0;" ::: "memory");
        __syncthreads();
        if (t + 1 < 16) { KV_LOAD(buf ^ 1, (t + 1) * 64); cp_commit(); }

        // ---- S = Q K^T (64x64): warp w -> rows (w>>2)*32, cols (w&3)*16
        {
            const int wm = w >> 2, wn = w & 3;
            const __half* Kb = Ks + buf * 64 * 72;
            wmma::fragment<wmma::accumulator, 16, 16, 16, float> s[2];
            wmma::fill_fragment(s[0], 0.0f);
            wmma::fill_fragment(s[1], 0.0f);
            #pragma unroll
            for (int kk = 0; kk < 64; kk += 16) {
                wmma::fragment<wmma::matrix_a, 16, 16, 16, __half, wmma::row_major> a[2];
                wmma::fragment<wmma::matrix_b, 16, 16, 16, __half, wmma::col_major> bf;
                #pragma unroll
                for (int i = 0; i < 2; i++)
                    wmma::load_matrix_sync(a[i], Qs + (wm * 32 + i * 16) * 72 + kk, 72);
                wmma::load_matrix_sync(bf, Kb + (wn * 16) * 72 + kk, 72);
                #pragma unroll
                for (int i = 0; i < 2; i++)
                    wmma::mma_sync(s[i], a[i], bf, s[i]);
            }
            #pragma unroll
            for (int i = 0; i < 2; i++)
                wmma::store_matrix_sync(&Ss[(wm * 32 + i * 16) * 68 + wn * 16],
                                        s[i], 68, wmma::mem_row_major);
        }
        __syncthreads();

        // ---- online softmax + O rescale (merged; alpha in registers) ----
        {
            const int q = q0 + rr;
            const int kbase = t * 64 + qr * 16;
            const float* lbrow = lb + (size_t)(b * LQ_ + q) * LK_ + kbase;
            float vals[16];
            float mx = -INFINITY;
            #pragma unroll
            for (int j = 0; j < 16; j += 4) {
                float4 sv = *(float4*)&Ss[rr * 68 + qr * 16 + j];
                float4 bv = *(const float4*)&lbrow[j];
                float o[4] = {sv.x + (mask_true(mask, kind, b * LK_ + kbase + j + 0) ? NEG_BIG : bv.x),
                              sv.y + (mask_true(mask, kind, b * LK_ + kbase + j + 1) ? NEG_BIG : bv.y),
                              sv.z + (mask_true(mask, kind, b * LK_ + kbase + j + 2) ? NEG_BIG : bv.z),
                              sv.w + (mask_true(mask, kind, b * LK_ + kbase + j + 3) ? NEG_BIG : bv.w)};
                #pragma unroll
                for (int e = 0; e < 4; e++) { vals[j + e] = o[e]; mx = fmaxf(mx, o[e]); }
            }
            mx = fmaxf(mx, __shfl_xor_sync(0xffffffffu, mx, 1));
            mx = fmaxf(mx, __shfl_xor_sync(0xffffffffu, mx, 2));

            // broadcast m_old from the row's qr==0 lane (shfl = sync point, no race)
            float mold = (qr == 0) ? m_s[rr] : 0.0f;
            mold = __shfl_sync(0xffffffffu, mold, lane & ~3);
            const float mnew = fmaxf(mold, mx);
            float sum = 0.0f;
            #pragma unroll
            for (int j = 0; j < 16; j += 2) {
                float p0 = __expf(vals[j] - mnew);
                float p1 = __expf(vals[j + 1] - mnew);
                sum += p0 + p1;
                *(__half2*)&Ps[rr * 72 + qr * 16 + j] = __floats2half2_rn(p0, p1);
            }
            sum += __shfl_xor_sync(0xffffffffu, sum, 1);
            sum += __shfl_xor_sync(0xffffffffu, sum, 2);
            const float alpha = __expf(mold - mnew);
            if (qr == 0) {
                l_s[rr] = l_s[rr] * alpha + sum;
                m_s[rr] = mnew;
            }
            // rescale this thread's O slice with register alpha
            float* orow = &Os[rr * 68 + qr * 16];
            #pragma unroll
            for (int j = 0; j < 16; j += 4) {
                float4 ov = *(float4*)&orow[j];
                ov.x *= alpha; ov.y *= alpha; ov.z *= alpha; ov.w *= alpha;
                *(float4*)&orow[j] = ov;
            }
        }
        __syncthreads();

        // ---- O += P V : warp w -> rows (w>>1)*16, cols (w&1)*32 (2 frags)
        {
            const int wm = w >> 1, wn = w & 1;
            const __half* Vb = Vs + buf * 64 * 72;
            wmma::fragment<wmma::accumulator, 16, 16, 16, float> c[2];
            #pragma unroll
            for (int j = 0; j < 2; j++)
                wmma::load_matrix_sync(c[j], &Os[(wm * 16) * 68 + wn * 32 + j * 16],
                                       68, wmma::mem_row_major);
            #pragma unroll
            for (int kk = 0; kk < 64; kk += 16) {
                wmma::fragment<wmma::matrix_a, 16, 16, 16, __half, wmma::row_major> a;
                wmma::fragment<wmma::matrix_b, 16, 16, 16, __half, wmma::row_major> bf[2];
                wmma::load_matrix_sync(a, Ps + (wm * 16) * 72 + kk, 72);
                #pragma unroll
                for (int j = 0; j < 2; j++)
                    wmma::load_matrix_sync(bf[j], Vb + kk * 72 + wn * 32 + j * 16, 72);
                #pragma unroll
                for (int j = 0; j < 2; j++)
                    wmma::mma_sync(c[j], a, bf[j], c[j]);
            }
            #pragma unroll
            for (int j = 0; j < 2; j++)
                wmma::store_matrix_sync(&Os[(wm * 16) * 68 + wn * 32 + j * 16],
                                        c[j], 68, wmma::mem_row_major);
        }
    }
    #undef KV_LOAD

    __syncthreads();
    // ---- normalize and write half output
    {
        const float inv = 1.0f / l_s[rr];
        const float* orow = &Os[rr * 68 + qr * 16];
        __half hv[16];
        #pragma unroll
        for (int j = 0; j < 16; j++) hv[j] = __float2half_rn(orow[j] * inv);
        __half* dst = &outh[(size_t)(b * LQ_ + q0 + rr) * 1024 + hc + qr * 16];
        *(uint4*)&dst[0] = *(uint4*)&hv[0];
        *(uint4*)&dst[8] = *(uint4*)&hv[8];
    }
}

// ---------------- launch ------------------------------------------------------
extern "C" void kernel_launch(void* const* d_in, const int* in_sizes, int n_in,
                              void* d_out, int out_size)
{
    const float* q    = (const float*)d_in[0];
    const float* k    = (const float*)d_in[1];
    const float* v    = (const float*)d_in[2];
    const float* Wq   = (const float*)d_in[3];
    const float* bq   = (const float*)d_in[4];
    const float* Wk   = (const float*)d_in[5];
    const float* bk   = (const float*)d_in[6];
    const float* Wv   = (const float*)d_in[7];
    const float* bv   = (const float*)d_in[8];
    const float* Wo   = (const float*)d_in[9];
    const float* bo   = (const float*)d_in[10];
    const float* lb   = (const float*)d_in[11];
    const void*  mask = (const void*)d_in[12];
    float* out = (float*)d_out;

    __half *xh3, *wh4, *qh, *kh, *vh;
    cudaGetSymbolAddress((void**)&xh3, g_xh3);
    cudaGetSymbolAddress((void**)&wh4, g_wh4);
    cudaGetSymbolAddress((void**)&qh, g_qh);
    cudaGetSymbolAddress((void**)&kh, g_kh);
    cudaGetSymbolAddress((void**)&vh, g_vh);

    cudaFuncSetAttribute(gemm_qkv,   cudaFuncAttributeMaxDynamicSharedMemorySize, GEMM_SMEM);
    cudaFuncSetAttribute(gemm_out,   cudaFuncAttributeMaxDynamicSharedMemorySize, GEMM_SMEM);
    cudaFuncSetAttribute(flash_attn, cudaFuncAttributeMaxDynamicSharedMemorySize, FLASH_SMEM);

    detect_mask_kernel<<<1, 32>>>((const unsigned int*)mask);

    // stage all inputs + weights to half (2 launches)
    cvt_qkv<<<dim3(1024, 1, 3), 256>>>(q, k, v, xh3);
    cvt_w4<<<dim3(512, 1, 4), 256>>>(Wq, Wk, Wv, Wo, wh4);

    // batched Q/K/V projections (one launch, 384 CTAs)
    gemm_qkv<<<dim3(8, 16, 3), 256, GEMM_SMEM>>>(xh3, wh4, bq, bk, bv, qh, kh, vh);

    // fused attention -> half att directly into staging slot 0
    flash_attn<<<dim3(LQ_ / 64, BH_), 256, FLASH_SMEM>>>(mask, lb, xh3);

    // output projection
    gemm_out<<<dim3(8, 16), 256, GEMM_SMEM>>>(xh3, wh4 + (size_t)3 * 1024 * 1024, bo, out);
}

// round 13
// speedup vs baseline: 3.9625x; 1.5118x over previous
#include <cuda_runtime.h>
#include <cuda_fp16.h>
#include <mma.h>
#include <math.h>
#include <cstdint>

using namespace nvcuda;

#define B_   2
#define LQ_  1024
#define LK_  1024
#define D_   1024
#define H_   16
#define DH_  64
#define BH_  (B_ * H_)
#define NEG_BIG (-3.402823466e38f)
#define L2E_ 1.44269504f

// ---------------- scratch ----------------------------------------------------
__device__ __half g_xh3[3 * 2048 * 1024];         // staged inputs q/k/v (half); slot0 reused for att
__device__ __half g_wh4[4 * 1024 * 1024];         // staged weights Wq/Wk/Wv/Wo (half)
__device__ __half g_qh[2048 * 1024];              // projected Q (half)
__device__ __half g_kh[2048 * 1024];              // projected K (half)
__device__ __half g_vh[2048 * 1024];              // projected V (half)
__device__ int    g_mask_kind;

// ---------------- helpers -----------------------------------------------------
__device__ __forceinline__ void cp16(unsigned int dst, const void* src) {
    asm volatile("cp.async.cg.shared.global [%0], [%1], 16;\n" :: "r"(dst), "l"(src));
}
__device__ __forceinline__ void cp_commit() {
    asm volatile("cp.async.commit_group;\n" ::: "memory");
}
__device__ __forceinline__ unsigned int smem_u32(const void* ptr) {
    unsigned int a;
    asm("{ .reg .u64 t; cvta.to.shared.u64 t, %1; cvt.u32.u64 %0, t; }" : "=r"(a) : "l"(ptr));
    return a;
}
__device__ __forceinline__ void ldsm4(unsigned& r0, unsigned& r1, unsigned& r2, unsigned& r3,
                                      unsigned addr) {
    asm volatile("ldmatrix.sync.aligned.m8n8.x4.shared.b16 {%0,%1,%2,%3}, [%4];"
                 : "=r"(r0), "=r"(r1), "=r"(r2), "=r"(r3) : "r"(addr));
}
__device__ __forceinline__ void ldsm4t(unsigned& r0, unsigned& r1, unsigned& r2, unsigned& r3,
                                       unsigned addr) {
    asm volatile("ldmatrix.sync.aligned.m8n8.x4.trans.shared.b16 {%0,%1,%2,%3}, [%4];"
                 : "=r"(r0), "=r"(r1), "=r"(r2), "=r"(r3) : "r"(addr));
}
__device__ __forceinline__ void ldsm2t(unsigned& r0, unsigned& r1, unsigned addr) {
    asm volatile("ldmatrix.sync.aligned.m8n8.x2.trans.shared.b16 {%0,%1}, [%2];"
                 : "=r"(r0), "=r"(r1) : "r"(addr));
}
__device__ __forceinline__ void mma16816(float* d, const unsigned* a, unsigned b0, unsigned b1) {
    asm volatile(
        "mma.sync.aligned.m16n8k16.row.col.f32.f16.f16.f32 "
        "{%0,%1,%2,%3}, {%4,%5,%6,%7}, {%8,%9}, {%0,%1,%2,%3};"
        : "+f"(d[0]), "+f"(d[1]), "+f"(d[2]), "+f"(d[3])
        : "r"(a[0]), "r"(a[1]), "r"(a[2]), "r"(a[3]), "r"(b0), "r"(b1));
}
__device__ __forceinline__ unsigned pack_ex2(float x, float y, float mn) {
    __half2 t = __floats2half2_rn((x - mn) * L2E_, (y - mn) * L2E_);
    unsigned u = *reinterpret_cast<unsigned*>(&t);
    unsigned r;
    asm("ex2.approx.f16x2 %0, %1;" : "=r"(r) : "r"(u));
    return r;
}

// ---------------- mask dtype detection --------------------------------------
__global__ void detect_mask_kernel(const unsigned int* m) {
    if (threadIdx.x == 0 && blockIdx.x == 0) {
        int all01 = 1, allf = 1;
        for (int i = 0; i < 512; i++) {
            unsigned v = m[i];
            if (v > 1u) all01 = 0;
            if (v != 0u && v != 0x3F800000u) allf = 0;
        }
        g_mask_kind = all01 ? 0 : (allf ? 1 : 2);
    }
}

__device__ __forceinline__ bool mask_true(const void* m, int kind, int idx) {
    if (kind == 0) return ((const int*)m)[idx] != 0;
    if (kind == 1) return ((const float*)m)[idx] != 0.0f;
    return ((const unsigned char*)m)[idx] != 0;
}

// ---------------- fp32 -> fp16 converts (batched) -----------------------------
__device__ __forceinline__ void cvt8(const float* __restrict__ x, __half* __restrict__ y, int i) {
    float4 a = *(const float4*)&x[i];
    float4 b = *(const float4*)&x[i + 4];
    __half h[8];
    h[0] = __float2half_rn(a.x); h[1] = __float2half_rn(a.y);
    h[2] = __float2half_rn(a.z); h[3] = __float2half_rn(a.w);
    h[4] = __float2half_rn(b.x); h[5] = __float2half_rn(b.y);
    h[6] = __float2half_rn(b.z); h[7] = __float2half_rn(b.w);
    *(uint4*)&y[i] = *(uint4*)h;
}

__global__ __launch_bounds__(256) void cvt_qkv(
    const float* __restrict__ x0, const float* __restrict__ x1,
    const float* __restrict__ x2, __half* __restrict__ y)
{
    const int z = blockIdx.z;
    const float* x = (z == 0) ? x0 : (z == 1) ? x1 : x2;
    cvt8(x, y + (size_t)z * 2048 * 1024, (blockIdx.x * 256 + threadIdx.x) * 8);
}

__global__ __launch_bounds__(256) void cvt_w4(
    const float* __restrict__ w0, const float* __restrict__ w1,
    const float* __restrict__ w2, const float* __restrict__ w3,
    __half* __restrict__ y)
{
    const int z = blockIdx.z;
    const float* x = (z == 0) ? w0 : (z == 1) ? w1 : (z == 2) ? w2 : w3;
    cvt8(x, y + (size_t)z * 1024 * 1024, (blockIdx.x * 256 + threadIdx.x) * 8);
}

// ---------------- fp16 GEMM core: C[2048,1024] = A @ W^T + bias --------------
#define GEMM_SMEM 73728

__device__ __forceinline__ void gemm_load_chunk(
    unsigned int sA, unsigned int sW, int buf, int m0, int n0, int kc0, int tid,
    const __half* __restrict__ A, const __half* __restrict__ Wm)
{
    #pragma unroll
    for (int u = 0; u < 4; u++) {
        int f = tid + u * 256;
        int r = f >> 3, ch = f & 7;
        unsigned int off = (unsigned int)(buf * 128 * 72 + r * 72 + ch * 8) * 2;
        cp16(sA + off, A + (size_t)(m0 + r) * 1024 + kc0 + ch * 8);
        cp16(sW + off, Wm + (size_t)(n0 + r) * 1024 + kc0 + ch * 8);
    }
}

__device__ __forceinline__ void gemm_core(
    char* smc, const __half* __restrict__ A, const __half* __restrict__ Wm,
    const float* __restrict__ bias, void* __restrict__ Cout, int out_is_half)
{
    __half* As = (__half*)smc;
    __half* Ws = As + 2 * 128 * 72;
    float*  Ss = (float*)smc;

    const int tid = threadIdx.x;
    const int w = tid >> 5;
    const int m0 = blockIdx.y * 128, n0 = blockIdx.x * 128;
    const int wm = w >> 2, wn = w & 3;

    const unsigned int sA = smem_u32(As);
    const unsigned int sW = smem_u32(Ws);

    wmma::fragment<wmma::accumulator, 16, 16, 16, float> c[4][2];
    #pragma unroll
    for (int i = 0; i < 4; i++)
        #pragma unroll
        for (int j = 0; j < 2; j++)
            wmma::fill_fragment(c[i][j], 0.0f);

    gemm_load_chunk(sA, sW, 0, m0, n0, 0,  tid, A, Wm); cp_commit();
    gemm_load_chunk(sA, sW, 1, m0, n0, 64, tid, A, Wm); cp_commit();

    for (int t = 0; t < 16; t++) {
        const int buf = t & 1;
        if (t == 15) asm volatile("cp.async.wait_group 0;" ::: "memory");
        else         asm volatile("cp.async.wait_group 1;" ::: "memory");
        __syncthreads();

        const __half* Ab = As + buf * 128 * 72;
        const __half* Wb = Ws + buf * 128 * 72;
        #pragma unroll
        for (int kk = 0; kk < 64; kk += 16) {
            wmma::fragment<wmma::matrix_a, 16, 16, 16, __half, wmma::row_major> a[4];
            wmma::fragment<wmma::matrix_b, 16, 16, 16, __half, wmma::col_major> bf[2];
            #pragma unroll
            for (int i = 0; i < 4; i++)
                wmma::load_matrix_sync(a[i], Ab + (wm * 64 + i * 16) * 72 + kk, 72);
            #pragma unroll
            for (int j = 0; j < 2; j++)
                wmma::load_matrix_sync(bf[j], Wb + (wn * 32 + j * 16) * 72 + kk, 72);
            #pragma unroll
            for (int i = 0; i < 4; i++)
                #pragma unroll
                for (int j = 0; j < 2; j++)
                    wmma::mma_sync(c[i][j], a[i], bf[j], c[i][j]);
        }
        __syncthreads();

        if (t + 2 < 16) {
            gemm_load_chunk(sA, sW, buf, m0, n0, (t + 2) * 64, tid, A, Wm);
            cp_commit();
        }
    }

    #pragma unroll
    for (int i = 0; i < 4; i++)
        #pragma unroll
        for (int j = 0; j < 2; j++)
            wmma::store_matrix_sync(&Ss[(wm * 64 + i * 16) * 132 + wn * 32 + j * 16],
                                    c[i][j], 132, wmma::mem_row_major);
    __syncthreads();

    if (out_is_half) {
        __half* C = (__half*)Cout;
        #pragma unroll
        for (int u = 0; u < 8; u++) {
            int f = tid + u * 256;
            int r = f >> 4, ch = f & 15;
            const float* src = &Ss[r * 132 + ch * 8];
            const float* bp = &bias[n0 + ch * 8];
            __half hv[8];
            #pragma unroll
            for (int e = 0; e < 8; e++) hv[e] = __float2half_rn(src[e] + bp[e]);
            *(uint4*)&C[(size_t)(m0 + r) * 1024 + n0 + ch * 8] = *(uint4*)hv;
        }
    } else {
        float* C = (float*)Cout;
        #pragma unroll
        for (int u = 0; u < 8; u++) {
            int f = tid + u * 256;
            int r = f >> 4, ch = f & 15;
            const float* src = &Ss[r * 132 + ch * 8];
            const float* bp = &bias[n0 + ch * 8];
            float ov[8];
            #pragma unroll
            for (int e = 0; e < 8; e++) ov[e] = src[e] + bp[e];
            *(float4*)&C[(size_t)(m0 + r) * 1024 + n0 + ch * 8] = *(float4*)ov;
            *(float4*)&C[(size_t)(m0 + r) * 1024 + n0 + ch * 8 + 4] = *(float4*)&ov[4];
        }
    }
}

// batched Q/K/V projection: grid (8,16,3)
__global__ __launch_bounds__(256) void gemm_qkv(
    const __half* __restrict__ Abase, const __half* __restrict__ Wbase,
    const float* __restrict__ b0, const float* __restrict__ b1, const float* __restrict__ b2,
    __half* __restrict__ C0, __half* __restrict__ C1, __half* __restrict__ C2)
{
    extern __shared__ char smc[];
    const int z = blockIdx.z;
    const float* bias = (z == 0) ? b0 : (z == 1) ? b1 : b2;
    __half* C = (z == 0) ? C0 : (z == 1) ? C1 : C2;
    gemm_core(smc, Abase + (size_t)z * 2048 * 1024,
              Wbase + (size_t)z * 1024 * 1024, bias, C, 1);
}

__global__ __launch_bounds__(256) void gemm_out(
    const __half* __restrict__ A, const __half* __restrict__ Wm,
    const float* __restrict__ bias, float* __restrict__ C)
{
    extern __shared__ char smc[];
    gemm_core(smc, A, Wm, bias, C, 0);
}

// ---------------- flash attention (FA2, register-resident) -------------------
// q-tile 128 (8 warps x 16 rows), k-tile 64, raw mma.m16n8k16 + ldmatrix.
// O and l in accumulator regs (l via ones-column of V). 1 barrier per k-tile.
// smem: msm[1024]f + Qs[128][72]h + Ks[2][64][72]h + Vs[2][64][72]h = 59392 B
#define FLASH_SMEM 59392

__global__ __launch_bounds__(256, 2) void flash_attn(
    const void* __restrict__ mask, const float* __restrict__ lb,
    __half* __restrict__ outh)
{
    extern __shared__ char smc[];
    float*  msm = (float*)smc;                     // [1024] mask additive
    __half* Qs = (__half*)(smc + 4096);            // [128][72]
    __half* Ks = Qs + 128 * 72;                    // [2][64][72]
    __half* Vs = Ks + 2 * 64 * 72;                 // [2][64][72]

    const int tid = threadIdx.x;
    const int w = tid >> 5, lane = tid & 31;
    const int q0 = blockIdx.x * 128;
    const int bh = blockIdx.y;
    const int b = bh >> 4, h = bh & 15;
    const int hc = h * DH_;
    const int kind = g_mask_kind;
    const int qw0 = w * 16;
    const int rowid = lane >> 2, cc2 = (lane & 3) * 2;

    const unsigned sQ = smem_u32(Qs);
    const unsigned sK = smem_u32(Ks);
    const unsigned sV = smem_u32(Vs);

    // mask additive row (shared by all q rows of this batch)
    for (int i = tid; i < 1024; i += 256)
        msm[i] = mask_true(mask, kind, b * LK_ + i) ? NEG_BIG : 0.0f;

    // stage Q (x0.125), 128x64 half
    const __half2 sc2 = __float2half2_rn(0.125f);
    #pragma unroll
    for (int u = 0; u < 4; u++) {
        int f = tid + u * 256;
        int r = f >> 3, ch = f & 7;
        uint4 qv = *(const uint4*)&g_qh[(size_t)(b * LQ_ + q0 + r) * 1024 + hc + ch * 8];
        __half2* qp = (__half2*)&qv;
        #pragma unroll
        for (int e = 0; e < 4; e++) qp[e] = __hmul2(qp[e], sc2);
        *(uint4*)&Qs[r * 72 + ch * 8] = qv;
    }
    // ones column (col 64) + zero pad (65..71) for V, both buffers
    for (int i = tid; i < 128; i += 256) {
        int bu = i >> 6, r = i & 63;
        uint4 z; z.x = 0x00003C00u; z.y = 0u; z.z = 0u; z.w = 0u;
        *(uint4*)&Vs[bu * 64 * 72 + r * 72 + 64] = z;
    }

    #define KV_LOAD(buf, kc0)                                                        \
    {                                                                                \
        _Pragma("unroll")                                                            \
        for (int u = 0; u < 2; u++) {                                                \
            int f = tid + u * 256;                                                   \
            int r = f >> 3, ch = f & 7;                                              \
            unsigned int off = (unsigned)((buf) * 64 * 72 + r * 72 + ch * 8) * 2;    \
            size_t g = (size_t)(b * LK_ + (kc0) + r) * 1024 + hc + ch * 8;           \
            cp16(sK + off, &g_kh[g]);                                                \
            cp16(sV + off, &g_vh[g]);                                                \
        }                                                                            \
    }

    KV_LOAD(0, 0); cp_commit();
    __syncthreads();

    // Q fragments (persistent): qa[ks][0..3]
    unsigned qa[4][4];
    {
        unsigned qaddr = sQ + (unsigned)((qw0 + ((lane >> 3) & 1) * 8 + (lane & 7)) * 144
                                         + (lane >> 4) * 16);
        #pragma unroll
        for (int ks = 0; ks < 4; ks++)
            ldsm4(qa[ks][0], qa[ks][1], qa[ks][2], qa[ks][3], qaddr + ks * 32);
    }

    // ldmatrix lane-offsets
    const unsigned koff = (unsigned)(((lane >> 4) * 8 + (lane & 7)) * 144 + ((lane >> 3) & 1) * 16);
    const unsigned voff = (unsigned)(((( lane >> 3) & 1) * 8 + (lane & 7)) * 144 + (lane >> 4) * 16);
    const unsigned ooff = (unsigned)(((( lane >> 3) & 1) * 8 + (lane & 7)) * 144 + 128);

    float oc[9][4];
    #pragma unroll
    for (int nt = 0; nt < 9; nt++)
        #pragma unroll
        for (int j = 0; j < 4; j++) oc[nt][j] = 0.0f;
    float m0 = NEG_BIG, m1 = NEG_BIG;

    const float* lbr0 = lb + (size_t)(b * LQ_ + q0 + qw0 + rowid) * 1024;
    const float* lbr1 = lbr0 + 8 * 1024;

    for (int t = 0; t < 16; t++) {
        const int buf = t & 1;
        asm volatile("cp.async.wait_group 0;" ::: "memory");
        __syncthreads();
        if (t + 1 < 16) { KV_LOAD(buf ^ 1, (t + 1) * 64); cp_commit(); }

        // ---- S = Q K^T (this warp: 16 rows x 64 cols) ----
        float s[8][4];
        #pragma unroll
        for (int nt = 0; nt < 8; nt++)
            #pragma unroll
            for (int j = 0; j < 4; j++) s[nt][j] = 0.0f;

        const unsigned kb = sK + (unsigned)(buf * 9216) + koff;
        #pragma unroll
        for (int ks = 0; ks < 4; ks++) {
            #pragma unroll
            for (int np = 0; np < 4; np++) {
                unsigned k0r, k1r, k2r, k3r;
                ldsm4(k0r, k1r, k2r, k3r, kb + np * 2304 + ks * 32);
                mma16816(s[2 * np],     qa[ks], k0r, k1r);
                mma16816(s[2 * np + 1], qa[ks], k2r, k3r);
            }
        }

        // ---- softmax (registers; P via ex2.f16x2) ----
        const int kb0 = t * 64 + cc2;
        float mx0 = NEG_BIG, mx1 = NEG_BIG;
        #pragma unroll
        for (int nt = 0; nt < 8; nt++) {
            float2 md = *(float2*)&msm[kb0 + nt * 8];
            float2 b0v = *(const float2*)&lbr0[kb0 + nt * 8];
            float2 b1v = *(const float2*)&lbr1[kb0 + nt * 8];
            s[nt][0] += b0v.x + md.x; s[nt][1] += b0v.y + md.y;
            s[nt][2] += b1v.x + md.x; s[nt][3] += b1v.y + md.y;
            mx0 = fmaxf(mx0, fmaxf(s[nt][0], s[nt][1]));
            mx1 = fmaxf(mx1, fmaxf(s[nt][2], s[nt][3]));
        }
        mx0 = fmaxf(mx0, __shfl_xor_sync(0xffffffffu, mx0, 1));
        mx0 = fmaxf(mx0, __shfl_xor_sync(0xffffffffu, mx0, 2));
        mx1 = fmaxf(mx1, __shfl_xor_sync(0xffffffffu, mx1, 1));
        mx1 = fmaxf(mx1, __shfl_xor_sync(0xffffffffu, mx1, 2));

        const float mn0 = fmaxf(m0, mx0), mn1 = fmaxf(m1, mx1);
        const float al0 = __expf(m0 - mn0), al1 = __expf(m1 - mn1);
        m0 = mn0; m1 = mn1;
        #pragma unroll
        for (int nt = 0; nt < 9; nt++) {
            oc[nt][0] *= al0; oc[nt][1] *= al0;
            oc[nt][2] *= al1; oc[nt][3] *= al1;
        }

        unsigned pa[4][4];
        #pragma unroll
        for (int ks = 0; ks < 4; ks++) {
            pa[ks][0] = pack_ex2(s[2 * ks][0],     s[2 * ks][1],     mn0);
            pa[ks][1] = pack_ex2(s[2 * ks][2],     s[2 * ks][3],     mn1);
            pa[ks][2] = pack_ex2(s[2 * ks + 1][0], s[2 * ks + 1][1], mn0);
            pa[ks][3] = pack_ex2(s[2 * ks + 1][2], s[2 * ks + 1][3], mn1);
        }

        // ---- O += P V  (+ ones column -> l in oc[8]) ----
        const unsigned vb = sV + (unsigned)(buf * 9216);
        #pragma unroll
        for (int ks = 0; ks < 4; ks++) {
            #pragma unroll
            for (int np = 0; np < 4; np++) {
                unsigned v0r, v1r, v2r, v3r;
                ldsm4t(v0r, v1r, v2r, v3r, vb + ks * 2304 + np * 32 + voff);
                mma16816(oc[2 * np],     pa[ks], v0r, v1r);
                mma16816(oc[2 * np + 1], pa[ks], v2r, v3r);
            }
            unsigned o0r, o1r;
            ldsm2t(o0r, o1r, vb + ks * 2304 + ooff);
            mma16816(oc[8], pa[ks], o0r, o1r);
        }
    }
    #undef KV_LOAD

    // ---- finalize: l = oc[8] col 64 (lane c==0), broadcast, normalize ----
    const float l0 = __shfl_sync(0xffffffffu, oc[8][0], lane & ~3);
    const float l1 = __shfl_sync(0xffffffffu, oc[8][2], lane & ~3);
    const float inv0 = 1.0f / l0, inv1 = 1.0f / l1;

    __half* d0 = &outh[(size_t)(b * LQ_ + q0 + qw0 + rowid) * 1024 + hc + cc2];
    __half* d1 = d0 + 8 * 1024;
    #pragma unroll
    for (int nt = 0; nt < 8; nt++) {
        *(__half2*)&d0[nt * 8] = __floats2half2_rn(oc[nt][0] * inv0, oc[nt][1] * inv0);
        *(__half2*)&d1[nt * 8] = __floats2half2_rn(oc[nt][2] * inv1, oc[nt][3] * inv1);
    }
}

// ---------------- launch ------------------------------------------------------
extern "C" void kernel_launch(void* const* d_in, const int* in_sizes, int n_in,
                              void* d_out, int out_size)
{
    const float* q    = (const float*)d_in[0];
    const float* k    = (const float*)d_in[1];
    const float* v    = (const float*)d_in[2];
    const float* Wq   = (const float*)d_in[3];
    const float* bq   = (const float*)d_in[4];
    const float* Wk   = (const float*)d_in[5];
    const float* bk   = (const float*)d_in[6];
    const float* Wv   = (const float*)d_in[7];
    const float* bv   = (const float*)d_in[8];
    const float* Wo   = (const float*)d_in[9];
    const float* bo   = (const float*)d_in[10];
    const float* lb   = (const float*)d_in[11];
    const void*  mask = (const void*)d_in[12];
    float* out = (float*)d_out;

    __half *xh3, *wh4, *qh, *kh, *vh;
    cudaGetSymbolAddress((void**)&xh3, g_xh3);
    cudaGetSymbolAddress((void**)&wh4, g_wh4);
    cudaGetSymbolAddress((void**)&qh, g_qh);
    cudaGetSymbolAddress((void**)&kh, g_kh);
    cudaGetSymbolAddress((void**)&vh, g_vh);

    cudaFuncSetAttribute(gemm_qkv,   cudaFuncAttributeMaxDynamicSharedMemorySize, GEMM_SMEM);
    cudaFuncSetAttribute(gemm_out,   cudaFuncAttributeMaxDynamicSharedMemorySize, GEMM_SMEM);
    cudaFuncSetAttribute(flash_attn, cudaFuncAttributeMaxDynamicSharedMemorySize, FLASH_SMEM);

    detect_mask_kernel<<<1, 32>>>((const unsigned int*)mask);

    // stage all inputs + weights to half (2 launches)
    cvt_qkv<<<dim3(1024, 1, 3), 256>>>(q, k, v, xh3);
    cvt_w4<<<dim3(512, 1, 4), 256>>>(Wq, Wk, Wv, Wo, wh4);

    // batched Q/K/V projections (one launch, 384 CTAs)
    gemm_qkv<<<dim3(8, 16, 3), 256, GEMM_SMEM>>>(xh3, wh4, bq, bk, bv, qh, kh, vh);

    // fused FA2 attention -> half att directly into staging slot 0
    flash_attn<<<dim3(LQ_ / 128, BH_), 256, FLASH_SMEM>>>(mask, lb, xh3);

    // output projection
    gemm_out<<<dim3(8, 16), 256, GEMM_SMEM>>>(xh3, wh4 + (size_t)3 * 1024 * 1024, bo, out);
}

// round 14
// speedup vs baseline: 4.0650x; 1.0259x over previous
#include <cuda_runtime.h>
#include <cuda_fp16.h>
#include <mma.h>
#include <math.h>
#include <cstdint>

using namespace nvcuda;

#define B_   2
#define LQ_  1024
#define LK_  1024
#define D_   1024
#define H_   16
#define DH_  64
#define BH_  (B_ * H_)
#define NEG_BIG (-3.402823466e38f)
#define L2E_ 1.44269504f

// ---------------- scratch ----------------------------------------------------
__device__ __half g_xh3[3 * 2048 * 1024];         // staged inputs q/k/v (half); slot0 reused for att
__device__ __half g_wh4[4 * 1024 * 1024];         // staged weights Wq/Wk/Wv/Wo (half)
__device__ __half g_qh[2048 * 1024];              // projected Q (half)
__device__ __half g_kh[2048 * 1024];              // projected K (half)
__device__ __half g_vh[2048 * 1024];              // projected V (half)
__device__ int    g_mask_kind;

// ---------------- helpers -----------------------------------------------------
__device__ __forceinline__ void cp16(unsigned int dst, const void* src) {
    asm volatile("cp.async.cg.shared.global [%0], [%1], 16;\n" :: "r"(dst), "l"(src));
}
__device__ __forceinline__ void cp_commit() {
    asm volatile("cp.async.commit_group;\n" ::: "memory");
}
__device__ __forceinline__ unsigned int smem_u32(const void* ptr) {
    unsigned int a;
    asm("{ .reg .u64 t; cvta.to.shared.u64 t, %1; cvt.u32.u64 %0, t; }" : "=r"(a) : "l"(ptr));
    return a;
}
__device__ __forceinline__ void ldsm4(unsigned& r0, unsigned& r1, unsigned& r2, unsigned& r3,
                                      unsigned addr) {
    asm volatile("ldmatrix.sync.aligned.m8n8.x4.shared.b16 {%0,%1,%2,%3}, [%4];"
                 : "=r"(r0), "=r"(r1), "=r"(r2), "=r"(r3) : "r"(addr));
}
__device__ __forceinline__ void ldsm4t(unsigned& r0, unsigned& r1, unsigned& r2, unsigned& r3,
                                       unsigned addr) {
    asm volatile("ldmatrix.sync.aligned.m8n8.x4.trans.shared.b16 {%0,%1,%2,%3}, [%4];"
                 : "=r"(r0), "=r"(r1), "=r"(r2), "=r"(r3) : "r"(addr));
}
__device__ __forceinline__ void ldsm2t(unsigned& r0, unsigned& r1, unsigned addr) {
    asm volatile("ldmatrix.sync.aligned.m8n8.x2.trans.shared.b16 {%0,%1}, [%2];"
                 : "=r"(r0), "=r"(r1) : "r"(addr));
}
__device__ __forceinline__ void mma16816(float* d, const unsigned* a, unsigned b0, unsigned b1) {
    asm volatile(
        "mma.sync.aligned.m16n8k16.row.col.f32.f16.f16.f32 "
        "{%0,%1,%2,%3}, {%4,%5,%6,%7}, {%8,%9}, {%0,%1,%2,%3};"
        : "+f"(d[0]), "+f"(d[1]), "+f"(d[2]), "+f"(d[3])
        : "r"(a[0]), "r"(a[1]), "r"(a[2]), "r"(a[3]), "r"(b0), "r"(b1));
}
__device__ __forceinline__ unsigned pack_ex2(float x, float y, float mn) {
    __half2 t = __floats2half2_rn((x - mn) * L2E_, (y - mn) * L2E_);
    unsigned u = *reinterpret_cast<unsigned*>(&t);
    unsigned r;
    asm("ex2.approx.f16x2 %0, %1;" : "=r"(r) : "r"(u));
    return r;
}

// ---------------- mask dtype detection --------------------------------------
__global__ void detect_mask_kernel(const unsigned int* m) {
    if (threadIdx.x == 0 && blockIdx.x == 0) {
        int all01 = 1, allf = 1;
        for (int i = 0; i < 512; i++) {
            unsigned v = m[i];
            if (v > 1u) all01 = 0;
            if (v != 0u && v != 0x3F800000u) allf = 0;
        }
        g_mask_kind = all01 ? 0 : (allf ? 1 : 2);
    }
}

__device__ __forceinline__ bool mask_true(const void* m, int kind, int idx) {
    if (kind == 0) return ((const int*)m)[idx] != 0;
    if (kind == 1) return ((const float*)m)[idx] != 0.0f;
    return ((const unsigned char*)m)[idx] != 0;
}

// ---------------- fp32 -> fp16 convert (single launch, 7 slices) -------------
__device__ __forceinline__ void cvt8(const float* __restrict__ x, __half* __restrict__ y, int i) {
    float4 a = *(const float4*)&x[i];
    float4 b = *(const float4*)&x[i + 4];
    __half h[8];
    h[0] = __float2half_rn(a.x); h[1] = __float2half_rn(a.y);
    h[2] = __float2half_rn(a.z); h[3] = __float2half_rn(a.w);
    h[4] = __float2half_rn(b.x); h[5] = __float2half_rn(b.y);
    h[6] = __float2half_rn(b.z); h[7] = __float2half_rn(b.w);
    *(uint4*)&y[i] = *(uint4*)h;
}

__global__ __launch_bounds__(256) void cvt_all(
    const float* __restrict__ q, const float* __restrict__ k, const float* __restrict__ v,
    const float* __restrict__ w0, const float* __restrict__ w1,
    const float* __restrict__ w2, const float* __restrict__ w3,
    __half* __restrict__ xh3, __half* __restrict__ wh4)
{
    const int z = blockIdx.z;
    const int i = (blockIdx.x * 256 + threadIdx.x) * 8;
    if (z < 3) {
        const float* x = (z == 0) ? q : (z == 1) ? k : v;
        cvt8(x, xh3 + (size_t)z * 2048 * 1024, i);
    } else {
        if (i >= 1024 * 1024) return;
        const int wz = z - 3;
        const float* x = (wz == 0) ? w0 : (wz == 1) ? w1 : (wz == 2) ? w2 : w3;
        cvt8(x, wh4 + (size_t)wz * 1024 * 1024, i);
    }
}

// ---------------- fp16 GEMM core: C[2048,1024] = A @ W^T + bias --------------
// BM=128 BN=128 BK=64; 3-stage cp.async pipeline; ONE barrier per K-iter.
// Stage layout (halves): [stage][ A[128][72] | W[128][72] ], stage stride 18432.
#define GEMM_SMEM 110592

__device__ __forceinline__ void gemm_load_stage(
    unsigned int sb, int stage, int m0, int n0, int kc0, int tid,
    const __half* __restrict__ A, const __half* __restrict__ Wm)
{
    const unsigned int base = (unsigned int)(stage * 18432) * 2;
    #pragma unroll
    for (int u = 0; u < 4; u++) {
        int f = tid + u * 256;
        int r = f >> 3, ch = f & 7;
        unsigned int off = base + (unsigned int)(r * 72 + ch * 8) * 2;
        cp16(sb + off,             A  + (size_t)(m0 + r) * 1024 + kc0 + ch * 8);
        cp16(sb + off + 9216 * 2,  Wm + (size_t)(n0 + r) * 1024 + kc0 + ch * 8);
    }
}

__device__ __forceinline__ void gemm_core(
    char* smc, const __half* __restrict__ A, const __half* __restrict__ Wm,
    const float* __restrict__ bias, void* __restrict__ Cout, int out_is_half)
{
    __half* Sh = (__half*)smc;
    float*  Ss = (float*)smc;      // epilogue reuse [128][132]

    const int tid = threadIdx.x;
    const int w = tid >> 5;
    const int m0 = blockIdx.y * 128, n0 = blockIdx.x * 128;
    const int wm = w >> 2, wn = w & 3;

    const unsigned int sb = smem_u32(Sh);

    wmma::fragment<wmma::accumulator, 16, 16, 16, float> c[4][2];
    #pragma unroll
    for (int i = 0; i < 4; i++)
        #pragma unroll
        for (int j = 0; j < 2; j++)
            wmma::fill_fragment(c[i][j], 0.0f);

    gemm_load_stage(sb, 0, m0, n0, 0,  tid, A, Wm); cp_commit();
    gemm_load_stage(sb, 1, m0, n0, 64, tid, A, Wm); cp_commit();

    for (int t = 0; t < 16; t++) {
        if (t == 15) asm volatile("cp.async.wait_group 0;" ::: "memory");
        else         asm volatile("cp.async.wait_group 1;" ::: "memory");
        __syncthreads();

        // prefetch t+2 into the stage last read at t-1 (all warps past it)
        if (t + 2 < 16) {
            int st; { int m3 = (t + 2) % 3; st = m3; }
            gemm_load_stage(sb, st, m0, n0, (t + 2) * 64, tid, A, Wm);
            cp_commit();
        }

        const __half* Ab = Sh + (t % 3) * 18432;
        const __half* Wb = Ab + 9216;
        #pragma unroll
        for (int kk = 0; kk < 64; kk += 16) {
            wmma::fragment<wmma::matrix_a, 16, 16, 16, __half, wmma::row_major> a[4];
            wmma::fragment<wmma::matrix_b, 16, 16, 16, __half, wmma::col_major> bf[2];
            #pragma unroll
            for (int i = 0; i < 4; i++)
                wmma::load_matrix_sync(a[i], Ab + (wm * 64 + i * 16) * 72 + kk, 72);
            #pragma unroll
            for (int j = 0; j < 2; j++)
                wmma::load_matrix_sync(bf[j], Wb + (wn * 32 + j * 16) * 72 + kk, 72);
            #pragma unroll
            for (int i = 0; i < 4; i++)
                #pragma unroll
                for (int j = 0; j < 2; j++)
                    wmma::mma_sync(c[i][j], a[i], bf[j], c[i][j]);
        }
    }

    __syncthreads();   // all compute done before smem reuse
    #pragma unroll
    for (int i = 0; i < 4; i++)
        #pragma unroll
        for (int j = 0; j < 2; j++)
            wmma::store_matrix_sync(&Ss[(wm * 64 + i * 16) * 132 + wn * 32 + j * 16],
                                    c[i][j], 132, wmma::mem_row_major);
    __syncthreads();

    if (out_is_half) {
        __half* C = (__half*)Cout;
        #pragma unroll
        for (int u = 0; u < 8; u++) {
            int f = tid + u * 256;
            int r = f >> 4, ch = f & 15;
            const float* src = &Ss[r * 132 + ch * 8];
            const float* bp = &bias[n0 + ch * 8];
            __half hv[8];
            #pragma unroll
            for (int e = 0; e < 8; e++) hv[e] = __float2half_rn(src[e] + bp[e]);
            *(uint4*)&C[(size_t)(m0 + r) * 1024 + n0 + ch * 8] = *(uint4*)hv;
        }
    } else {
        float* C = (float*)Cout;
        #pragma unroll
        for (int u = 0; u < 8; u++) {
            int f = tid + u * 256;
            int r = f >> 4, ch = f & 15;
            const float* src = &Ss[r * 132 + ch * 8];
            const float* bp = &bias[n0 + ch * 8];
            float ov[8];
            #pragma unroll
            for (int e = 0; e < 8; e++) ov[e] = src[e] + bp[e];
            *(float4*)&C[(size_t)(m0 + r) * 1024 + n0 + ch * 8] = *(float4*)ov;
            *(float4*)&C[(size_t)(m0 + r) * 1024 + n0 + ch * 8 + 4] = *(float4*)&ov[4];
        }
    }
}

// batched Q/K/V projection: grid (8,16,3)
__global__ __launch_bounds__(256) void gemm_qkv(
    const __half* __restrict__ Abase, const __half* __restrict__ Wbase,
    const float* __restrict__ b0, const float* __restrict__ b1, const float* __restrict__ b2,
    __half* __restrict__ C0, __half* __restrict__ C1, __half* __restrict__ C2)
{
    extern __shared__ char smc[];
    const int z = blockIdx.z;
    const float* bias = (z == 0) ? b0 : (z == 1) ? b1 : b2;
    __half* C = (z == 0) ? C0 : (z == 1) ? C1 : C2;
    gemm_core(smc, Abase + (size_t)z * 2048 * 1024,
              Wbase + (size_t)z * 1024 * 1024, bias, C, 1);
}

__global__ __launch_bounds__(256) void gemm_out(
    const __half* __restrict__ A, const __half* __restrict__ Wm,
    const float* __restrict__ bias, float* __restrict__ C)
{
    extern __shared__ char smc[];
    gemm_core(smc, A, Wm, bias, C, 0);
}

// ---------------- flash attention (FA2, register-resident) -------------------
// q-tile 128 (8 warps x 16 rows), k-tile 64, raw mma.m16n8k16 + ldmatrix.
// O and l in accumulator regs (l via ones-column of V). 1 barrier per k-tile.
// smem: msm[1024]f + Qs[128][72]h + Ks[2][64][72]h + Vs[2][64][72]h = 59392 B
#define FLASH_SMEM 59392

__global__ __launch_bounds__(256, 2) void flash_attn(
    const void* __restrict__ mask, const float* __restrict__ lb,
    __half* __restrict__ outh)
{
    extern __shared__ char smc[];
    float*  msm = (float*)smc;                     // [1024] mask additive
    __half* Qs = (__half*)(smc + 4096);            // [128][72]
    __half* Ks = Qs + 128 * 72;                    // [2][64][72]
    __half* Vs = Ks + 2 * 64 * 72;                 // [2][64][72]

    const int tid = threadIdx.x;
    const int w = tid >> 5, lane = tid & 31;
    const int q0 = blockIdx.x * 128;
    const int bh = blockIdx.y;
    const int b = bh >> 4, h = bh & 15;
    const int hc = h * DH_;
    const int kind = g_mask_kind;
    const int qw0 = w * 16;
    const int rowid = lane >> 2, cc2 = (lane & 3) * 2;

    const unsigned sQ = smem_u32(Qs);
    const unsigned sK = smem_u32(Ks);
    const unsigned sV = smem_u32(Vs);

    // mask additive row (shared by all q rows of this batch)
    for (int i = tid; i < 1024; i += 256)
        msm[i] = mask_true(mask, kind, b * LK_ + i) ? NEG_BIG : 0.0f;

    // stage Q (x0.125), 128x64 half
    const __half2 sc2 = __float2half2_rn(0.125f);
    #pragma unroll
    for (int u = 0; u < 4; u++) {
        int f = tid + u * 256;
        int r = f >> 3, ch = f & 7;
        uint4 qv = *(const uint4*)&g_qh[(size_t)(b * LQ_ + q0 + r) * 1024 + hc + ch * 8];
        __half2* qp = (__half2*)&qv;
        #pragma unroll
        for (int e = 0; e < 4; e++) qp[e] = __hmul2(qp[e], sc2);
        *(uint4*)&Qs[r * 72 + ch * 8] = qv;
    }
    // ones column (col 64) + zero pad (65..71) for V, both buffers
    for (int i = tid; i < 128; i += 256) {
        int bu = i >> 6, r = i & 63;
        uint4 z; z.x = 0x00003C00u; z.y = 0u; z.z = 0u; z.w = 0u;
        *(uint4*)&Vs[bu * 64 * 72 + r * 72 + 64] = z;
    }

    #define KV_LOAD(buf, kc0)                                                        \
    {                                                                                \
        _Pragma("unroll")                                                            \
        for (int u = 0; u < 2; u++) {                                                \
            int f = tid + u * 256;                                                   \
            int r = f >> 3, ch = f & 7;                                              \
            unsigned int off = (unsigned)((buf) * 64 * 72 + r * 72 + ch * 8) * 2;    \
            size_t g = (size_t)(b * LK_ + (kc0) + r) * 1024 + hc + ch * 8;           \
            cp16(sK + off, &g_kh[g]);                                                \
            cp16(sV + off, &g_vh[g]);                                                \
        }                                                                            \
    }

    KV_LOAD(0, 0); cp_commit();
    __syncthreads();

    // Q fragments (persistent): qa[ks][0..3]
    unsigned qa[4][4];
    {
        unsigned qaddr = sQ + (unsigned)((qw0 + ((lane >> 3) & 1) * 8 + (lane & 7)) * 144
                                         + (lane >> 4) * 16);
        #pragma unroll
        for (int ks = 0; ks < 4; ks++)
            ldsm4(qa[ks][0], qa[ks][1], qa[ks][2], qa[ks][3], qaddr + ks * 32);
    }

    // ldmatrix lane-offsets
    const unsigned koff = (unsigned)(((lane >> 4) * 8 + (lane & 7)) * 144 + ((lane >> 3) & 1) * 16);
    const unsigned voff = (unsigned)(((( lane >> 3) & 1) * 8 + (lane & 7)) * 144 + (lane >> 4) * 16);
    const unsigned ooff = (unsigned)(((( lane >> 3) & 1) * 8 + (lane & 7)) * 144 + 128);

    float oc[9][4];
    #pragma unroll
    for (int nt = 0; nt < 9; nt++)
        #pragma unroll
        for (int j = 0; j < 4; j++) oc[nt][j] = 0.0f;
    float m0 = NEG_BIG, m1 = NEG_BIG;

    const float* lbr0 = lb + (size_t)(b * LQ_ + q0 + qw0 + rowid) * 1024;
    const float* lbr1 = lbr0 + 8 * 1024;

    for (int t = 0; t < 16; t++) {
        const int buf = t & 1;
        asm volatile("cp.async.wait_group 0;" ::: "memory");
        __syncthreads();
        if (t + 1 < 16) { KV_LOAD(buf ^ 1, (t + 1) * 64); cp_commit(); }

        // ---- S = Q K^T (this warp: 16 rows x 64 cols) ----
        float s[8][4];
        #pragma unroll
        for (int nt = 0; nt < 8; nt++)
            #pragma unroll
            for (int j = 0; j < 4; j++) s[nt][j] = 0.0f;

        const unsigned kb = sK + (unsigned)(buf * 9216) + koff;
        #pragma unroll
        for (int ks = 0; ks < 4; ks++) {
            #pragma unroll
            for (int np = 0; np < 4; np++) {
                unsigned k0r, k1r, k2r, k3r;
                ldsm4(k0r, k1r, k2r, k3r, kb + np * 2304 + ks * 32);
                mma16816(s[2 * np],     qa[ks], k0r, k1r);
                mma16816(s[2 * np + 1], qa[ks], k2r, k3r);
            }
        }

        // ---- softmax (registers; P via ex2.f16x2) ----
        const int kb0 = t * 64 + cc2;
        float mx0 = NEG_BIG, mx1 = NEG_BIG;
        #pragma unroll
        for (int nt = 0; nt < 8; nt++) {
            float2 md = *(float2*)&msm[kb0 + nt * 8];
            float2 b0v = *(const float2*)&lbr0[kb0 + nt * 8];
            float2 b1v = *(const float2*)&lbr1[kb0 + nt * 8];
            s[nt][0] += b0v.x + md.x; s[nt][1] += b0v.y + md.y;
            s[nt][2] += b1v.x + md.x; s[nt][3] += b1v.y + md.y;
            mx0 = fmaxf(mx0, fmaxf(s[nt][0], s[nt][1]));
            mx1 = fmaxf(mx1, fmaxf(s[nt][2], s[nt][3]));
        }
        mx0 = fmaxf(mx0, __shfl_xor_sync(0xffffffffu, mx0, 1));
        mx0 = fmaxf(mx0, __shfl_xor_sync(0xffffffffu, mx0, 2));
        mx1 = fmaxf(mx1, __shfl_xor_sync(0xffffffffu, mx1, 1));
        mx1 = fmaxf(mx1, __shfl_xor_sync(0xffffffffu, mx1, 2));

        const float mn0 = fmaxf(m0, mx0), mn1 = fmaxf(m1, mx1);
        const float al0 = __expf(m0 - mn0), al1 = __expf(m1 - mn1);
        m0 = mn0; m1 = mn1;
        #pragma unroll
        for (int nt = 0; nt < 9; nt++) {
            oc[nt][0] *= al0; oc[nt][1] *= al0;
            oc[nt][2] *= al1; oc[nt][3] *= al1;
        }

        unsigned pa[4][4];
        #pragma unroll
        for (int ks = 0; ks < 4; ks++) {
            pa[ks][0] = pack_ex2(s[2 * ks][0],     s[2 * ks][1],     mn0);
            pa[ks][1] = pack_ex2(s[2 * ks][2],     s[2 * ks][3],     mn1);
            pa[ks][2] = pack_ex2(s[2 * ks + 1][0], s[2 * ks + 1][1], mn0);
            pa[ks][3] = pack_ex2(s[2 * ks + 1][2], s[2 * ks + 1][3], mn1);
        }

        // ---- O += P V  (+ ones column -> l in oc[8]) ----
        const unsigned vb = sV + (unsigned)(buf * 9216);
        #pragma unroll
        for (int ks = 0; ks < 4; ks++) {
            #pragma unroll
            for (int np = 0; np < 4; np++) {
                unsigned v0r, v1r, v2r, v3r;
                ldsm4t(v0r, v1r, v2r, v3r, vb + ks * 2304 + np * 32 + voff);
                mma16816(oc[2 * np],     pa[ks], v0r, v1r);
                mma16816(oc[2 * np + 1], pa[ks], v2r, v3r);
            }
            unsigned o0r, o1r;
            ldsm2t(o0r, o1r, vb + ks * 2304 + ooff);
            mma16816(oc[8], pa[ks], o0r, o1r);
        }
    }
    #undef KV_LOAD

    // ---- finalize: l = oc[8] col 64 (lane c==0), broadcast, normalize ----
    const float l0 = __shfl_sync(0xffffffffu, oc[8][0], lane & ~3);
    const float l1 = __shfl_sync(0xffffffffu, oc[8][2], lane & ~3);
    const float inv0 = 1.0f / l0, inv1 = 1.0f / l1;

    __half* d0 = &outh[(size_t)(b * LQ_ + q0 + qw0 + rowid) * 1024 + hc + cc2];
    __half* d1 = d0 + 8 * 1024;
    #pragma unroll
    for (int nt = 0; nt < 8; nt++) {
        *(__half2*)&d0[nt * 8] = __floats2half2_rn(oc[nt][0] * inv0, oc[nt][1] * inv0);
        *(__half2*)&d1[nt * 8] = __floats2half2_rn(oc[nt][2] * inv1, oc[nt][3] * inv1);
    }
}

// ---------------- launch ------------------------------------------------------
extern "C" void kernel_launch(void* const* d_in, const int* in_sizes, int n_in,
                              void* d_out, int out_size)
{
    const float* q    = (const float*)d_in[0];
    const float* k    = (const float*)d_in[1];
    const float* v    = (const float*)d_in[2];
    const float* Wq   = (const float*)d_in[3];
    const float* bq   = (const float*)d_in[4];
    const float* Wk   = (const float*)d_in[5];
    const float* bk   = (const float*)d_in[6];
    const float* Wv   = (const float*)d_in[7];
    const float* bv   = (const float*)d_in[8];
    const float* Wo   = (const float*)d_in[9];
    const float* bo   = (const float*)d_in[10];
    const float* lb   = (const float*)d_in[11];
    const void*  mask = (const void*)d_in[12];
    float* out = (float*)d_out;

    __half *xh3, *wh4, *qh, *kh, *vh;
    cudaGetSymbolAddress((void**)&xh3, g_xh3);
    cudaGetSymbolAddress((void**)&wh4, g_wh4);
    cudaGetSymbolAddress((void**)&qh, g_qh);
    cudaGetSymbolAddress((void**)&kh, g_kh);
    cudaGetSymbolAddress((void**)&vh, g_vh);

    cudaFuncSetAttribute(gemm_qkv,   cudaFuncAttributeMaxDynamicSharedMemorySize, GEMM_SMEM);
    cudaFuncSetAttribute(gemm_out,   cudaFuncAttributeMaxDynamicSharedMemorySize, GEMM_SMEM);
    cudaFuncSetAttribute(flash_attn, cudaFuncAttributeMaxDynamicSharedMemorySize, FLASH_SMEM);

    detect_mask_kernel<<<1, 32>>>((const unsigned int*)mask);

    // stage all inputs + weights to half (ONE launch)
    cvt_all<<<dim3(1024, 1, 7), 256>>>(q, k, v, Wq, Wk, Wv, Wo, xh3, wh4);

    // batched Q/K/V projections (one launch, 384 CTAs)
    gemm_qkv<<<dim3(8, 16, 3), 256, GEMM_SMEM>>>(xh3, wh4, bq, bk, bv, qh, kh, vh);

    // fused FA2 attention -> half att directly into staging slot 0
    flash_attn<<<dim3(LQ_ / 128, BH_), 256, FLASH_SMEM>>>(mask, lb, xh3);

    // output projection
    gemm_out<<<dim3(8, 16), 256, GEMM_SMEM>>>(xh3, wh4 + (size_t)3 * 1024 * 1024, bo, out);
}